// round 10
// baseline (speedup 1.0000x reference)
#include <cuda_runtime.h>
#include <math.h>
#include <stdint.h>

#define B_   2
#define T_   2048
#define DM_  1024
#define DP_  6432
#define DI_  2048
#define H_   32
#define P_   64
#define N_   64
#define L_   128
#define NC_  16
#define RB_  (B_*T_)          /* 4096 rows */
#define SCALE_F 0.08838834764831845f  /* 1/sqrt(128) */
#define EPS_F 1e-6f

/* ------------------------------------------------------------------ */
/* scratch (static device globals: allocation-free, graph-safe)        */
/* ------------------------------------------------------------------ */
__device__ float g_proj[(size_t)RB_ * DP_];       /* 105 MB */
__device__ float g_logdA[RB_ * H_];
__device__ float g_acoef[RB_ * H_];
__device__ float g_bcoef[RB_ * H_];
__device__ float g_mt[RB_ * H_];
__device__ float g_cosb[RB_ * H_];
__device__ float g_sinb[RB_ * H_];
__device__ float g_cum[RB_ * H_];
__device__ float g_Bn[RB_ * 128];
__device__ float g_Cn[RB_ * 64];
__device__ float g_Br[RB_ * 128];
__device__ float g_Cr[RB_ * 64];
__device__ float g_st[(size_t)B_ * NC_ * H_ * N_ * P_];
__device__ float g_Sprev[(size_t)B_ * NC_ * H_ * N_ * P_];
__device__ float g_y[(size_t)RB_ * DI_];
/* shared (head-independent) C.B dot matrix: [b*16+c][l:128][v:258 pad 264] */
__device__ float g_D[(size_t)B_ * NC_ * 128 * 264];

/* ------------------------------------------------------------------ */
/* bf16x3 tensor-core GEMM (R6 version: convert-in-smem).              */
/* ------------------------------------------------------------------ */
#define AST_STRIDE 36
#define BST_STRIDE 132
#define AST_SIZE (128*AST_STRIDE)
#define BST_SIZE (32*BST_STRIDE)
#define AP_STRIDE 20
#define BP_STRIDE 136
#define AP_SIZE  (128*AP_STRIDE)
#define BP_SIZE  (16*BP_STRIDE)
#define OFF_AST  0
#define OFF_BST  (2*AST_SIZE)
#define OFF_AH   (OFF_BST + 2*BST_SIZE)
#define OFF_AL   (OFF_AH + AP_SIZE)
#define OFF_BH   (OFF_AL + AP_SIZE)
#define OFF_BL   (OFF_BH + BP_SIZE)
#define GEMM_WORDS (OFF_BL + BP_SIZE)
#define GEMM_SMEM_BYTES (GEMM_WORDS * 4)

__device__ __forceinline__ uint32_t smem_u32(const void* p) {
    return (uint32_t)__cvta_generic_to_shared(p);
}
__device__ __forceinline__ void cp16(uint32_t dst, const void* src, int pred_bytes) {
    asm volatile("cp.async.cg.shared.global [%0], [%1], 16, %2;"
                 :: "r"(dst), "l"(src), "r"(pred_bytes));
}
__device__ __forceinline__ void f2bf2(float x0, float x1, uint32_t& h, uint32_t& l) {
    asm("cvt.rn.bf16x2.f32 %0, %1, %2;" : "=r"(h) : "f"(x1), "f"(x0));
    float h0 = __uint_as_float(h << 16);
    float h1 = __uint_as_float(h & 0xffff0000u);
    float l0 = x0 - h0, l1 = x1 - h1;
    asm("cvt.rn.bf16x2.f32 %0, %1, %2;" : "=r"(l) : "f"(l1), "f"(l0));
}
__device__ __forceinline__ void mma16(float* c, const uint32_t* a, const uint32_t* b) {
    asm volatile(
        "mma.sync.aligned.m16n8k16.row.col.f32.bf16.bf16.f32 "
        "{%0,%1,%2,%3}, {%4,%5,%6,%7}, {%8,%9}, {%0,%1,%2,%3};"
        : "+f"(c[0]), "+f"(c[1]), "+f"(c[2]), "+f"(c[3])
        : "r"(a[0]), "r"(a[1]), "r"(a[2]), "r"(a[3]), "r"(b[0]), "r"(b[1]));
}

__global__ __launch_bounds__(256, 2) void gemm_bf16x3(
    const float* __restrict__ A, const float* __restrict__ Bm,
    float* __restrict__ C, int M, int N, int K)
{
    extern __shared__ float sm[];
    float* ASt = sm + OFF_AST;
    float* BSt = sm + OFF_BST;
    uint32_t* Ah = (uint32_t*)(sm + OFF_AH);
    uint32_t* Al = (uint32_t*)(sm + OFF_AL);
    uint32_t* Bh = (uint32_t*)(sm + OFF_BH);
    uint32_t* Bl = (uint32_t*)(sm + OFF_BL);

    int tid = threadIdx.x;
    int bm = blockIdx.y * 128, bn = blockIdx.x * 128;
    int warp = tid >> 5, lane = tid & 31;
    int gid = lane >> 2, tig = lane & 3;
    int wm = (warp & 1) * 64;
    int wn = (warp >> 1) * 32;

    float acc[4][4][4];
#pragma unroll
    for (int mt = 0; mt < 4; mt++)
#pragma unroll
        for (int nt = 0; nt < 4; nt++)
#pragma unroll
            for (int q = 0; q < 4; q++) acc[mt][nt][q] = 0.f;

    int KTn = K >> 5;

#define PREFETCH(ktv, buf)                                                      \
    {                                                                           \
        int k0 = (ktv) << 5;                                                    \
        float* Ab_ = ASt + (buf) * AST_SIZE;                                    \
        float* Bb_ = BSt + (buf) * BST_SIZE;                                    \
        _Pragma("unroll")                                                       \
        for (int i = 0; i < 4; i++) {                                           \
            int idx = tid + i * 256;                                            \
            int row = idx >> 3, kc = (idx & 7) << 2;                            \
            cp16(smem_u32(&Ab_[row * AST_STRIDE + kc]),                         \
                 A + (size_t)(bm + row) * K + k0 + kc, 16);                     \
        }                                                                       \
        _Pragma("unroll")                                                       \
        for (int i = 0; i < 4; i++) {                                           \
            int idx = tid + i * 256;                                            \
            int row = idx >> 5, nc = (idx & 31) << 2;                           \
            int ok = (bn + nc) < N;                                             \
            const float* src = ok ? (Bm + (size_t)(k0 + row) * N + bn + nc) : Bm; \
            cp16(smem_u32(&Bb_[row * BST_STRIDE + nc]), src, ok ? 16 : 0);      \
        }                                                                       \
        asm volatile("cp.async.commit_group;");                                 \
    }

    PREFETCH(0, 0);

    for (int kt = 0; kt < KTn; kt++) {
        if (kt + 1 < KTn) {
            PREFETCH(kt + 1, (kt + 1) & 1);
            asm volatile("cp.async.wait_group 1;");
        } else {
            asm volatile("cp.async.wait_group 0;");
        }
        __syncthreads();

        {
            const float* Ab = ASt + (kt & 1) * AST_SIZE;
            const float* Bb = BSt + (kt & 1) * BST_SIZE;
            int mq = tid >> 4, kpA = tid & 15;
#pragma unroll
            for (int j = 0; j < 8; j++) {
                int m = j * 16 + mq;
                float2 v = *(const float2*)&Ab[m * AST_STRIDE + 2 * kpA];
                uint32_t hh, ll;
                f2bf2(v.x, v.y, hh, ll);
                Ah[m * AP_STRIDE + kpA] = hh;
                Al[m * AP_STRIDE + kpA] = ll;
            }
            int n = tid & 127, kq = tid >> 7;
#pragma unroll
            for (int j = 0; j < 8; j++) {
                int kp = j * 2 + kq;
                float b0 = Bb[(2 * kp) * BST_STRIDE + n];
                float b1 = Bb[(2 * kp + 1) * BST_STRIDE + n];
                uint32_t hh, ll;
                f2bf2(b0, b1, hh, ll);
                Bh[kp * BP_STRIDE + n] = hh;
                Bl[kp * BP_STRIDE + n] = ll;
            }
        }
        __syncthreads();

#pragma unroll
        for (int ks = 0; ks < 2; ks++) {
            int kp0 = ks * 8 + tig;
            uint32_t bh[4][2], bl[4][2];
#pragma unroll
            for (int nt = 0; nt < 4; nt++) {
                int n = wn + nt * 8 + gid;
                bh[nt][0] = Bh[kp0 * BP_STRIDE + n];
                bh[nt][1] = Bh[(kp0 + 4) * BP_STRIDE + n];
                bl[nt][0] = Bl[kp0 * BP_STRIDE + n];
                bl[nt][1] = Bl[(kp0 + 4) * BP_STRIDE + n];
            }
#pragma unroll
            for (int mt = 0; mt < 4; mt++) {
                int m0 = wm + mt * 16 + gid;
                uint32_t ah[4], al[4];
                ah[0] = Ah[m0 * AP_STRIDE + kp0];
                ah[1] = Ah[(m0 + 8) * AP_STRIDE + kp0];
                ah[2] = Ah[m0 * AP_STRIDE + kp0 + 4];
                ah[3] = Ah[(m0 + 8) * AP_STRIDE + kp0 + 4];
                al[0] = Al[m0 * AP_STRIDE + kp0];
                al[1] = Al[(m0 + 8) * AP_STRIDE + kp0];
                al[2] = Al[m0 * AP_STRIDE + kp0 + 4];
                al[3] = Al[(m0 + 8) * AP_STRIDE + kp0 + 4];
#pragma unroll
                for (int nt = 0; nt < 4; nt++) {
                    mma16(acc[mt][nt], ah, bh[nt]);
                    mma16(acc[mt][nt], al, bh[nt]);
                    mma16(acc[mt][nt], ah, bl[nt]);
                }
            }
        }
        __syncthreads();
    }

#pragma unroll
    for (int mt = 0; mt < 4; mt++) {
#pragma unroll
        for (int nt = 0; nt < 4; nt++) {
            int row0 = bm + wm + mt * 16 + gid;
            int col = bn + wn + nt * 8 + tig * 2;
            if (col < N) {
                *(float2*)&C[(size_t)row0 * N + col] =
                    make_float2(acc[mt][nt][0], acc[mt][nt][1]);
                *(float2*)&C[(size_t)(row0 + 8) * N + col] =
                    make_float2(acc[mt][nt][2], acc[mt][nt][3]);
            }
        }
    }
}

/* ------------------------------------------------------------------ */
/* 2. per-(b,t): dt/lambda/alpha + coefs, RMS of B/C, silu(x), mt      */
/* ------------------------------------------------------------------ */
__global__ __launch_bounds__(128) void act_kernel(
    const float* __restrict__ A_log, const float* __restrict__ dt_bias,
    const float* __restrict__ Bnb, const float* __restrict__ Cnb)
{
    int row = blockIdx.x;
    float* pr = g_proj + (size_t)row * DP_;
    int tid = threadIdx.x, lane = tid & 31, w = tid >> 5;
    __shared__ float red[8];

    if (w == 0) {
        int h = lane;
        float xr = pr[6336 + h] + dt_bias[h];
        float sp = (xr > 20.f) ? xr : log1pf(expf(xr));
        float dt = fminf(fmaxf(sp, 1e-4f), 0.5f);
        float A = -expf(A_log[h]);
        float ldA = dt * A;
        float lam = 1.f / (1.f + expf(-pr[6368 + h]));
        g_logdA[row * 32 + h] = ldA;
        g_acoef[row * 32 + h] = lam * dt;
        g_bcoef[row * 32 + h] = (1.f - lam) * dt * expf(ldA);
        float s = dt;
#pragma unroll
        for (int o = 16; o > 0; o >>= 1) s += __shfl_xor_sync(0xffffffffu, s, o);
        float md = s * (1.f / 32.f);
        g_mt[row * 32 + h] = md * pr[6400 + h];
    }

    float bv = pr[6144 + tid];
    float ss = bv * bv;
#pragma unroll
    for (int o = 16; o > 0; o >>= 1) ss += __shfl_xor_sync(0xffffffffu, ss, o);
    if (lane == 0) red[w] = ss;
    __syncthreads();
    {
        int r = tid >> 6, n = tid & 63;
        float sum = red[r * 2] + red[r * 2 + 1];
        g_Bn[(size_t)row * 128 + tid] = bv * rsqrtf(sum * (1.f / 64.f) + EPS_F) * Bnb[n];
    }

    float cv = 0.f, ss2 = 0.f;
    if (tid < 64) {
        cv = pr[6272 + tid];
        ss2 = cv * cv;
#pragma unroll
        for (int o = 16; o > 0; o >>= 1) ss2 += __shfl_xor_sync(0xffffffffu, ss2, o);
        if (lane == 0) red[4 + w] = ss2;
    }
    __syncthreads();
    if (tid < 64) {
        float sum = red[4] + red[5];
        g_Cn[(size_t)row * 64 + tid] = cv * rsqrtf(sum * (1.f / 64.f) + EPS_F) * Cnb[tid];
    }

    for (int j = tid; j < 4096; j += 128) {
        float v = pr[2048 + j];
        pr[2048 + j] = v / (1.f + expf(-v));
    }
}

/* ------------------------------------------------------------------ */
/* 3. full-T inclusive scan of mean_dt*theta -> cos/sin of -cumsum     */
/* ------------------------------------------------------------------ */
__global__ __launch_bounds__(256) void scan_ang_kernel()
{
    int bk = blockIdx.x;
    int b = bk >> 5, k = bk & 31;
    int tid = threadIdx.x;
    size_t base = ((size_t)b * T_) * 32 + k;
    float v[8];
    float run = 0.f;
#pragma unroll
    for (int j = 0; j < 8; j++) {
        run += g_mt[base + (size_t)(tid * 8 + j) * 32];
        v[j] = run;
    }
    __shared__ float s[256];
    s[tid] = run;
    __syncthreads();
    for (int off = 1; off < 256; off <<= 1) {
        float xv = (tid >= off) ? s[tid - off] : 0.f;
        __syncthreads();
        s[tid] += xv;
        __syncthreads();
    }
    float excl = s[tid] - run;
#pragma unroll
    for (int j = 0; j < 8; j++) {
        float ang = -(excl + v[j]);
        size_t idx = base + (size_t)(tid * 8 + j) * 32;
        g_cosb[idx] = cosf(ang);
        g_sinb[idx] = sinf(ang);
    }
}

/* ------------------------------------------------------------------ */
/* 4. RoPE for C and B(r=0,1)                                          */
/* ------------------------------------------------------------------ */
__global__ __launch_bounds__(32) void rope_kernel()
{
    int row = blockIdx.x;
    int k = threadIdx.x;
    float cs = g_cosb[(size_t)row * 32 + k], sn = g_sinb[(size_t)row * 32 + k];
    float c1 = g_Cn[(size_t)row * 64 + k], c2 = g_Cn[(size_t)row * 64 + 32 + k];
    g_Cr[(size_t)row * 64 + k] = c1 * cs - c2 * sn;
    g_Cr[(size_t)row * 64 + 32 + k] = c1 * sn + c2 * cs;
#pragma unroll
    for (int r = 0; r < 2; r++) {
        float b1 = g_Bn[(size_t)row * 128 + r * 64 + k];
        float b2 = g_Bn[(size_t)row * 128 + r * 64 + 32 + k];
        g_Br[(size_t)row * 128 + r * 64 + k] = b1 * cs - b2 * sn;
        g_Br[(size_t)row * 128 + r * 64 + 32 + k] = b1 * sn + b2 * cs;
    }
}

/* ------------------------------------------------------------------ */
/* 5. within-chunk inclusive cumsum of log dA (smem-staged)            */
/* ------------------------------------------------------------------ */
__global__ __launch_bounds__(128) void cum_kernel()
{
    __shared__ float s[128 * 32];
    int blk = blockIdx.x;
    int tid = threadIdx.x;
    size_t base = (size_t)blk * 128 * 32;
    for (int i = tid; i < 4096; i += 128) s[i] = g_logdA[base + i];
    __syncthreads();
    if (tid < 32) {
        float run = 0.f;
        for (int l = 0; l < 128; l++) {
            run += s[l * 32 + tid];
            s[l * 32 + tid] = run;
        }
    }
    __syncthreads();
    for (int i = tid; i < 4096; i += 128) g_cum[base + i] = s[i];
}

/* ------------------------------------------------------------------ */
/* 5b. s_kernel: per (b,c) shared dot matrix                           */
/* ------------------------------------------------------------------ */
#define SC_STRIDE 69
#define SBS_STRIDE 133
#define SMEM_S_FLOATS (128*SC_STRIDE + 129*SBS_STRIDE)
__global__ __launch_bounds__(256) void s_kernel()
{
    extern __shared__ float sm[];
    float* sC = sm;
    float* sB = sm + 128 * SC_STRIDE;
    int c = blockIdx.x, b = blockIdx.y;
    int tid = threadIdx.x;
    int t0 = c * L_;
    size_t rb = (size_t)b * T_ + t0;

    for (int i = tid; i < 128 * 64; i += 256) {
        int l = i >> 6, n = i & 63;
        sC[l * SC_STRIDE + n] = g_Cr[(rb + l) * 64 + n];
    }
    for (int i = tid; i < 129 * 128; i += 256) {
        int row = i >> 7, j = i & 127;
        int t = t0 + row - 1;
        sB[row * SBS_STRIDE + j] = (t >= 0) ? g_Br[((size_t)b * T_ + t) * 128 + j] : 0.f;
    }
    __syncthreads();

    int lt = tid >> 3;
    int vg = tid & 7;
    float* gD = g_D + (size_t)(b * 16 + c) * 128 * 264;

#pragma unroll
    for (int pass = 0; pass < 5; pass++) {
        int v0 = pass * 64 + vg * 8;
        if (v0 < 258) {
            int boff[8];
#pragma unroll
            for (int u = 0; u < 8; u++) {
                int v = v0 + u; if (v > 257) v = 257;
                boff[u] = (v >> 1) * SBS_STRIDE + (v & 1) * 64;
            }
            float acc[4][8];
#pragma unroll
            for (int q = 0; q < 4; q++)
#pragma unroll
                for (int u = 0; u < 8; u++) acc[q][u] = 0.f;
            const float* cp = sC + (lt * 4) * SC_STRIDE;
            for (int k = 0; k < 64; k++) {
                float cv[4];
#pragma unroll
                for (int q = 0; q < 4; q++) cv[q] = cp[q * SC_STRIDE + k];
                float bv[8];
#pragma unroll
                for (int u = 0; u < 8; u++) bv[u] = sB[boff[u] + k];
#pragma unroll
                for (int q = 0; q < 4; q++)
#pragma unroll
                    for (int u = 0; u < 8; u++) acc[q][u] += cv[q] * bv[u];
            }
#pragma unroll
            for (int q = 0; q < 4; q++) {
                float* drow = gD + (size_t)(lt * 4 + q) * 264 + v0;
#pragma unroll
                for (int u = 0; u < 8; u++)
                    if (v0 + u < 258) drow[u] = acc[q][u];
            }
        }
    }
}

/* ------------------------------------------------------------------ */
/* 6. fused per-(b,c,h) chunk kernel: y_intra + chunk state st         */
/* factorized decay (branch-free), R6 loop structure                   */
/* ------------------------------------------------------------------ */
#define SMEM_CHUNK_FLOATS 39324
__global__ __launch_bounds__(256) void chunk_kernel()
{
    extern __shared__ float sm[];
    float* sB   = sm;             /* 17028 */
    float* sX   = sm + 17028;     /* 17028 */
    float* sD   = sm + 34056;     /* 4608  */
    float* sCum = sm + 38664;     /* 128   */
    float* sA   = sm + 38792;     /* 128   */
    float* sBc  = sm + 38920;     /* 128   */
    float* sDE  = sm + 39048;     /* 128   */
    float* sEl  = sm + 39176;     /* 128   */
    float* sEm  = sm + 39304;     /* 16    */

    int h = blockIdx.x, c = blockIdx.y, b = blockIdx.z;
    int tid = threadIdx.x;
    int t0 = c * L_;
    size_t rb = (size_t)b * T_ + t0;
    const float* gD = g_D + (size_t)(b * 16 + c) * 128 * 264;

    for (int i = tid; i < 129 * 128; i += 256) {
        int row = i >> 7, j = i & 127;
        int t = t0 + row - 1;
        sB[row * 132 + j] = (t >= 0) ? g_Br[((size_t)b * T_ + t) * 128 + j] : 0.f;
    }
    for (int i = tid; i < 129 * 128; i += 256) {
        int row = i >> 7, j = i & 127;
        int t = t0 + row - 1;
        sX[row * 132 + j] = (t >= 0)
            ? g_proj[((size_t)b * T_ + t) * DP_ + 2048 + h * 128 + j] : 0.f;
    }
    if (tid < 128) {
        size_t g = (rb + tid) * 32 + h;
        sCum[tid] = g_cum[g];
        sA[tid] = g_acoef[g];
        sBc[tid] = g_bcoef[g];
    }
    __syncthreads();
    if (tid < 128) sDE[tid] = expf(sCum[127] - sCum[tid]);

    float acc[8][4];
#pragma unroll
    for (int i = 0; i < 8; i++)
#pragma unroll
        for (int q = 0; q < 4; q++) acc[i][q] = 0.f;

    int pg = tid & 15, p0 = pg << 2, lg = tid >> 4;

    for (int m0 = 0; m0 < 128; m0 += 16) {
        int rows = 128 - m0;
        float base = sCum[m0];
        /* factorized decay pieces (shared, cheap) */
        if (tid < rows) sEl[tid] = expf(sCum[m0 + tid] - base);
        if (tid < 16)  sEm[tid] = SCALE_F * expf(base - sCum[m0 + tid]);
        /* load shared dot tile rows l >= m0 */
        for (int e = tid; e < rows * 34; e += 256) {
            int lr = e / 34;
            int rem = e - lr * 34;
            int l = m0 + lr;
            sD[l * 36 + rem] = gD[(size_t)l * 264 + m0 * 2 + rem];
        }
        __syncthreads();

        float el[8];
#pragma unroll
        for (int jl = 0; jl < 8; jl++) {
            int lr = lg + (jl << 4) - m0;
            el[jl] = (lr >= 0) ? sEl[lr] : 0.f;
        }

        for (int mm = 0; mm < 16; mm++) {
            int m = m0 + mm;
            float em = sEm[mm];
            float ea = sA[m], eb = sBc[m];
            float4 xga = *(const float4*)&sX[(m + 1) * 132 + p0];
            float4 xgb = *(const float4*)&sX[(m + 1) * 132 + 64 + p0];
            float4 xba = *(const float4*)&sX[m * 132 + p0];
            float4 xbb = *(const float4*)&sX[m * 132 + 64 + p0];
            float xg0[4] = {ea * xga.x, ea * xga.y, ea * xga.z, ea * xga.w};
            float xg1[4] = {ea * xgb.x, ea * xgb.y, ea * xgb.z, ea * xgb.w};
            float xb0[4] = {eb * xba.x, eb * xba.y, eb * xba.z, eb * xba.w};
            float xb1[4] = {eb * xbb.x, eb * xbb.y, eb * xbb.z, eb * xbb.w};
#pragma unroll
            for (int jl = 0; jl < 8; jl++) {
                int l = lg + (jl << 4);
                float gc = (l >= m) ? el[jl] * em : 0.f;   /* FSEL, no branch */
                float d1r0 = sD[l * 36 + (mm + 1) * 2];
                float d1r1 = sD[l * 36 + (mm + 1) * 2 + 1];
                float d0r0 = sD[l * 36 + mm * 2];
                float d0r1 = sD[l * 36 + mm * 2 + 1];
#pragma unroll
                for (int q = 0; q < 4; q++) {
                    float tq = d1r0 * xg0[q] + d1r1 * xg1[q]
                             + d0r0 * xb0[q] + d0r1 * xb1[q];
                    acc[jl][q] += gc * tq;
                }
            }
        }
        __syncthreads();
    }
#pragma unroll
    for (int jl = 0; jl < 8; jl++) {
        int l = lg + (jl << 4);
        float4 outv = make_float4(acc[jl][0], acc[jl][1], acc[jl][2], acc[jl][3]);
        *(float4*)&g_y[(rb + l) * (size_t)DI_ + h * 64 + p0] = outv;
    }

    int p = tid & 63, ng = tid >> 6;
    float st[16];
#pragma unroll
    for (int jn = 0; jn < 16; jn++) st[jn] = 0.f;
    for (int m = 0; m < 128; m++) {
        float e = sDE[m];
        float eg = e * sA[m], ebk = e * sBc[m];
        float xg0 = eg * sX[(m + 1) * 132 + p];
        float xg1 = eg * sX[(m + 1) * 132 + 64 + p];
        float xb0 = ebk * sX[m * 132 + p];
        float xb1 = ebk * sX[m * 132 + 64 + p];
        const float* bg = &sB[(m + 1) * 132];
        const float* bb = &sB[m * 132];
#pragma unroll
        for (int jn = 0; jn < 16; jn++) {
            int n = ng * 16 + jn;
            st[jn] += bg[n] * xg0 + bg[64 + n] * xg1 + bb[n] * xb0 + bb[64 + n] * xb1;
        }
    }
    size_t so = (((size_t)(b * 16 + c) * 32 + h) * 4096);
#pragma unroll
    for (int jn = 0; jn < 16; jn++)
        g_st[so + (size_t)(ng * 16 + jn) * 64 + p] = st[jn];
}

/* ------------------------------------------------------------------ */
/* 7. inter-chunk state scan (16 steps)                                */
/* ------------------------------------------------------------------ */
__global__ __launch_bounds__(256) void scan_chunks_kernel()
{
    int b = blockIdx.x >> 5, h = blockIdx.x & 31;
    int tid = threadIdx.x;
    float S[16];
#pragma unroll
    for (int j = 0; j < 16; j++) S[j] = 0.f;
    for (int c = 0; c < 16; c++) {
        float cdec = expf(g_cum[((size_t)(b * 2048 + c * 128 + 127)) * 32 + h]);
        size_t off0 = (((size_t)(b * 16 + c) * 32 + h) * 4096);
#pragma unroll
        for (int j = 0; j < 16; j++) {
            size_t off = off0 + tid + j * 256;
            g_Sprev[off] = S[j];
            S[j] = cdec * S[j] + g_st[off];
        }
    }
}

/* ------------------------------------------------------------------ */
/* 8. y += SCALE * dec_in * (C @ Sprev)                                */
/* ------------------------------------------------------------------ */
#define SMEM_INTER_FLOATS (64*68 + 128*68 + 128)
__global__ __launch_bounds__(256) void inter_kernel()
{
    extern __shared__ float sm[];
    float* sS = sm;
    float* sC = sm + 64 * 68;
    float* sDec = sC + 128 * 68;
    int h = blockIdx.x, c = blockIdx.y, b = blockIdx.z;
    int tid = threadIdx.x;
    int t0 = c * 128;
    size_t rb = (size_t)b * T_ + t0;
    size_t soff = (((size_t)(b * 16 + c) * 32 + h) * 4096);

    for (int i = tid; i < 4096; i += 256)
        sS[(i >> 6) * 68 + (i & 63)] = g_Sprev[soff + i];
    for (int i = tid; i < 128 * 64; i += 256) {
        int l = i >> 6, n = i & 63;
        sC[l * 68 + n] = g_Cr[(rb + l) * 64 + n];
    }
    if (tid < 128) sDec[tid] = expf(g_cum[(rb + tid) * 32 + h]);
    __syncthreads();

    int pg = tid & 15, p0 = pg << 2, lg = tid >> 4;
#pragma unroll
    for (int jl = 0; jl < 8; jl++) {
        int l = lg + (jl << 4);
        float a0 = 0.f, a1 = 0.f, a2 = 0.f, a3 = 0.f;
#pragma unroll
        for (int n = 0; n < 64; n++) {
            float cv = sC[l * 68 + n];
            const float* sp = &sS[n * 68 + p0];
            a0 += cv * sp[0]; a1 += cv * sp[1];
            a2 += cv * sp[2]; a3 += cv * sp[3];
        }
        float coef = SCALE_F * sDec[l];
        float* yp = &g_y[(rb + l) * (size_t)DI_ + h * 64 + p0];
        yp[0] += coef * a0; yp[1] += coef * a1;
        yp[2] += coef * a2; yp[3] += coef * a3;
    }
}

/* ------------------------------------------------------------------ */
/* 9. y = rms(y * silu(z))                                             */
/* ------------------------------------------------------------------ */
__global__ __launch_bounds__(256) void gate_kernel()
{
    int row = blockIdx.x;
    int tid = threadIdx.x, lane = tid & 31, w = tid >> 5;
    const float* z = g_proj + (size_t)row * DP_;
    float* y = g_y + (size_t)row * DI_;
    float v[8];
    float ss = 0.f;
#pragma unroll
    for (int j = 0; j < 8; j++) {
        int i = tid + j * 256;
        float zv = z[i];
        float sz = zv / (1.f + expf(-zv));
        float vv = y[i] * sz;
        v[j] = vv;
        ss += vv * vv;
    }
#pragma unroll
    for (int o = 16; o > 0; o >>= 1) ss += __shfl_xor_sync(0xffffffffu, ss, o);
    __shared__ float red[8];
    if (lane == 0) red[w] = ss;
    __syncthreads();
    float tot = red[0] + red[1] + red[2] + red[3] + red[4] + red[5] + red[6] + red[7];
    float rinv = rsqrtf(tot * (1.f / 2048.f) + EPS_F);
#pragma unroll
    for (int j = 0; j < 8; j++) y[tid + j * 256] = v[j] * rinv;
}

/* ------------------------------------------------------------------ */
extern "C" void kernel_launch(void* const* d_in, const int* in_sizes, int n_in,
                              void* d_out, int out_size)
{
    const float* x       = (const float*)d_in[0];
    const float* W_in    = (const float*)d_in[1];
    const float* A_log   = (const float*)d_in[2];
    const float* dt_bias = (const float*)d_in[3];
    const float* Bnb     = (const float*)d_in[4];
    const float* Cnb     = (const float*)d_in[5];
    const float* W_out   = (const float*)d_in[6];
    float* out = (float*)d_out;

    void *p_proj = 0, *p_y = 0;
    cudaGetSymbolAddress(&p_proj, g_proj);
    cudaGetSymbolAddress(&p_y, g_y);

    cudaFuncSetAttribute(gemm_bf16x3, cudaFuncAttributeMaxDynamicSharedMemorySize,
                         GEMM_SMEM_BYTES);
    cudaFuncSetAttribute(s_kernel, cudaFuncAttributeMaxDynamicSharedMemorySize,
                         SMEM_S_FLOATS * 4);
    cudaFuncSetAttribute(chunk_kernel, cudaFuncAttributeMaxDynamicSharedMemorySize,
                         SMEM_CHUNK_FLOATS * 4);
    cudaFuncSetAttribute(inter_kernel, cudaFuncAttributeMaxDynamicSharedMemorySize,
                         SMEM_INTER_FLOATS * 4);

    /* 1. in-proj */
    gemm_bf16x3<<<dim3((DP_ + 127) / 128, RB_ / 128), 256, GEMM_SMEM_BYTES>>>(
        x, W_in, (float*)p_proj, RB_, DP_, DM_);
    /* 2. activations */
    act_kernel<<<RB_, 128>>>(A_log, dt_bias, Bnb, Cnb);
    /* 3. angle scan */
    scan_ang_kernel<<<B_ * 32, 256>>>();
    /* 4. rope */
    rope_kernel<<<RB_, 32>>>();
    /* 5. chunk cumsum */
    cum_kernel<<<B_ * NC_, 128>>>();
    /* 5b. shared dot matrix */
    s_kernel<<<dim3(NC_, B_), 256, SMEM_S_FLOATS * 4>>>();
    /* 6. fused chunk */
    chunk_kernel<<<dim3(H_, NC_, B_), 256, SMEM_CHUNK_FLOATS * 4>>>();
    /* 7. state scan */
    scan_chunks_kernel<<<B_ * H_, 256>>>();
    /* 8. inter */
    inter_kernel<<<dim3(H_, NC_, B_), 256, SMEM_INTER_FLOATS * 4>>>();
    /* 9. gate + rms */
    gate_kernel<<<RB_, 256>>>();
    /* 10. out-proj */
    gemm_bf16x3<<<dim3(DM_ / 128, RB_ / 128), 256, GEMM_SMEM_BYTES>>>(
        (const float*)p_y, W_out, out, RB_, DM_, DI_);
}

// round 11
// speedup vs baseline: 1.0311x; 1.0311x over previous
#include <cuda_runtime.h>
#include <math.h>
#include <stdint.h>

#define B_   2
#define T_   2048
#define DM_  1024
#define DP_  6432
#define DI_  2048
#define H_   32
#define P_   64
#define N_   64
#define L_   128
#define NC_  16
#define RB_  (B_*T_)          /* 4096 rows */
#define SCALE_F 0.08838834764831845f  /* 1/sqrt(128) */
#define EPS_F 1e-6f

/* ------------------------------------------------------------------ */
/* scratch (static device globals: allocation-free, graph-safe)        */
/* ------------------------------------------------------------------ */
__device__ float g_proj[(size_t)RB_ * DP_];       /* 105 MB */
__device__ float g_logdA[RB_ * H_];
__device__ float g_acoef[RB_ * H_];
__device__ float g_bcoef[RB_ * H_];
__device__ float g_mt[RB_ * H_];
__device__ float g_cosb[RB_ * H_];
__device__ float g_sinb[RB_ * H_];
__device__ float g_cum[RB_ * H_];
__device__ float g_Bn[RB_ * 128];
__device__ float g_Cn[RB_ * 64];
__device__ float g_Br[RB_ * 128];
__device__ float g_Cr[RB_ * 64];
__device__ float g_st[(size_t)B_ * NC_ * H_ * N_ * P_];
__device__ float g_Sprev[(size_t)B_ * NC_ * H_ * N_ * P_];
__device__ float g_y[(size_t)RB_ * DI_];
/* shared (head-independent) C.B dot matrix: [b*16+c][l:128][v:258 pad 264] */
__device__ float g_D[(size_t)B_ * NC_ * 128 * 264];

/* ------------------------------------------------------------------ */
/* bf16x3 tensor-core GEMM (R6 version: convert-in-smem).              */
/* ------------------------------------------------------------------ */
#define AST_STRIDE 36
#define BST_STRIDE 132
#define AST_SIZE (128*AST_STRIDE)
#define BST_SIZE (32*BST_STRIDE)
#define AP_STRIDE 20
#define BP_STRIDE 136
#define AP_SIZE  (128*AP_STRIDE)
#define BP_SIZE  (16*BP_STRIDE)
#define OFF_AST  0
#define OFF_BST  (2*AST_SIZE)
#define OFF_AH   (OFF_BST + 2*BST_SIZE)
#define OFF_AL   (OFF_AH + AP_SIZE)
#define OFF_BH   (OFF_AL + AP_SIZE)
#define OFF_BL   (OFF_BH + BP_SIZE)
#define GEMM_WORDS (OFF_BL + BP_SIZE)
#define GEMM_SMEM_BYTES (GEMM_WORDS * 4)

__device__ __forceinline__ uint32_t smem_u32(const void* p) {
    return (uint32_t)__cvta_generic_to_shared(p);
}
__device__ __forceinline__ void cp16(uint32_t dst, const void* src, int pred_bytes) {
    asm volatile("cp.async.cg.shared.global [%0], [%1], 16, %2;"
                 :: "r"(dst), "l"(src), "r"(pred_bytes));
}
__device__ __forceinline__ void f2bf2(float x0, float x1, uint32_t& h, uint32_t& l) {
    asm("cvt.rn.bf16x2.f32 %0, %1, %2;" : "=r"(h) : "f"(x1), "f"(x0));
    float h0 = __uint_as_float(h << 16);
    float h1 = __uint_as_float(h & 0xffff0000u);
    float l0 = x0 - h0, l1 = x1 - h1;
    asm("cvt.rn.bf16x2.f32 %0, %1, %2;" : "=r"(l) : "f"(l1), "f"(l0));
}
__device__ __forceinline__ void mma16(float* c, const uint32_t* a, const uint32_t* b) {
    asm volatile(
        "mma.sync.aligned.m16n8k16.row.col.f32.bf16.bf16.f32 "
        "{%0,%1,%2,%3}, {%4,%5,%6,%7}, {%8,%9}, {%0,%1,%2,%3};"
        : "+f"(c[0]), "+f"(c[1]), "+f"(c[2]), "+f"(c[3])
        : "r"(a[0]), "r"(a[1]), "r"(a[2]), "r"(a[3]), "r"(b[0]), "r"(b[1]));
}

__global__ __launch_bounds__(256, 2) void gemm_bf16x3(
    const float* __restrict__ A, const float* __restrict__ Bm,
    float* __restrict__ C, int M, int N, int K)
{
    extern __shared__ float sm[];
    float* ASt = sm + OFF_AST;
    float* BSt = sm + OFF_BST;
    uint32_t* Ah = (uint32_t*)(sm + OFF_AH);
    uint32_t* Al = (uint32_t*)(sm + OFF_AL);
    uint32_t* Bh = (uint32_t*)(sm + OFF_BH);
    uint32_t* Bl = (uint32_t*)(sm + OFF_BL);

    int tid = threadIdx.x;
    int bm = blockIdx.y * 128, bn = blockIdx.x * 128;
    int warp = tid >> 5, lane = tid & 31;
    int gid = lane >> 2, tig = lane & 3;
    int wm = (warp & 1) * 64;
    int wn = (warp >> 1) * 32;

    float acc[4][4][4];
#pragma unroll
    for (int mt = 0; mt < 4; mt++)
#pragma unroll
        for (int nt = 0; nt < 4; nt++)
#pragma unroll
            for (int q = 0; q < 4; q++) acc[mt][nt][q] = 0.f;

    int KTn = K >> 5;

#define PREFETCH(ktv, buf)                                                      \
    {                                                                           \
        int k0 = (ktv) << 5;                                                    \
        float* Ab_ = ASt + (buf) * AST_SIZE;                                    \
        float* Bb_ = BSt + (buf) * BST_SIZE;                                    \
        _Pragma("unroll")                                                       \
        for (int i = 0; i < 4; i++) {                                           \
            int idx = tid + i * 256;                                            \
            int row = idx >> 3, kc = (idx & 7) << 2;                            \
            cp16(smem_u32(&Ab_[row * AST_STRIDE + kc]),                         \
                 A + (size_t)(bm + row) * K + k0 + kc, 16);                     \
        }                                                                       \
        _Pragma("unroll")                                                       \
        for (int i = 0; i < 4; i++) {                                           \
            int idx = tid + i * 256;                                            \
            int row = idx >> 5, nc = (idx & 31) << 2;                           \
            int ok = (bn + nc) < N;                                             \
            const float* src = ok ? (Bm + (size_t)(k0 + row) * N + bn + nc) : Bm; \
            cp16(smem_u32(&Bb_[row * BST_STRIDE + nc]), src, ok ? 16 : 0);      \
        }                                                                       \
        asm volatile("cp.async.commit_group;");                                 \
    }

    PREFETCH(0, 0);

    for (int kt = 0; kt < KTn; kt++) {
        if (kt + 1 < KTn) {
            PREFETCH(kt + 1, (kt + 1) & 1);
            asm volatile("cp.async.wait_group 1;");
        } else {
            asm volatile("cp.async.wait_group 0;");
        }
        __syncthreads();

        {
            const float* Ab = ASt + (kt & 1) * AST_SIZE;
            const float* Bb = BSt + (kt & 1) * BST_SIZE;
            int mq = tid >> 4, kpA = tid & 15;
#pragma unroll
            for (int j = 0; j < 8; j++) {
                int m = j * 16 + mq;
                float2 v = *(const float2*)&Ab[m * AST_STRIDE + 2 * kpA];
                uint32_t hh, ll;
                f2bf2(v.x, v.y, hh, ll);
                Ah[m * AP_STRIDE + kpA] = hh;
                Al[m * AP_STRIDE + kpA] = ll;
            }
            int n = tid & 127, kq = tid >> 7;
#pragma unroll
            for (int j = 0; j < 8; j++) {
                int kp = j * 2 + kq;
                float b0 = Bb[(2 * kp) * BST_STRIDE + n];
                float b1 = Bb[(2 * kp + 1) * BST_STRIDE + n];
                uint32_t hh, ll;
                f2bf2(b0, b1, hh, ll);
                Bh[kp * BP_STRIDE + n] = hh;
                Bl[kp * BP_STRIDE + n] = ll;
            }
        }
        __syncthreads();

#pragma unroll
        for (int ks = 0; ks < 2; ks++) {
            int kp0 = ks * 8 + tig;
            uint32_t bh[4][2], bl[4][2];
#pragma unroll
            for (int nt = 0; nt < 4; nt++) {
                int n = wn + nt * 8 + gid;
                bh[nt][0] = Bh[kp0 * BP_STRIDE + n];
                bh[nt][1] = Bh[(kp0 + 4) * BP_STRIDE + n];
                bl[nt][0] = Bl[kp0 * BP_STRIDE + n];
                bl[nt][1] = Bl[(kp0 + 4) * BP_STRIDE + n];
            }
#pragma unroll
            for (int mt = 0; mt < 4; mt++) {
                int m0 = wm + mt * 16 + gid;
                uint32_t ah[4], al[4];
                ah[0] = Ah[m0 * AP_STRIDE + kp0];
                ah[1] = Ah[(m0 + 8) * AP_STRIDE + kp0];
                ah[2] = Ah[m0 * AP_STRIDE + kp0 + 4];
                ah[3] = Ah[(m0 + 8) * AP_STRIDE + kp0 + 4];
                al[0] = Al[m0 * AP_STRIDE + kp0];
                al[1] = Al[(m0 + 8) * AP_STRIDE + kp0];
                al[2] = Al[m0 * AP_STRIDE + kp0 + 4];
                al[3] = Al[(m0 + 8) * AP_STRIDE + kp0 + 4];
#pragma unroll
                for (int nt = 0; nt < 4; nt++) {
                    mma16(acc[mt][nt], ah, bh[nt]);
                    mma16(acc[mt][nt], al, bh[nt]);
                    mma16(acc[mt][nt], ah, bl[nt]);
                }
            }
        }
        __syncthreads();
    }

#pragma unroll
    for (int mt = 0; mt < 4; mt++) {
#pragma unroll
        for (int nt = 0; nt < 4; nt++) {
            int row0 = bm + wm + mt * 16 + gid;
            int col = bn + wn + nt * 8 + tig * 2;
            if (col < N) {
                *(float2*)&C[(size_t)row0 * N + col] =
                    make_float2(acc[mt][nt][0], acc[mt][nt][1]);
                *(float2*)&C[(size_t)(row0 + 8) * N + col] =
                    make_float2(acc[mt][nt][2], acc[mt][nt][3]);
            }
        }
    }
}

/* ------------------------------------------------------------------ */
/* 2. per-(b,t): dt/lambda/alpha + coefs, RMS of B/C, silu(x), mt      */
/* ------------------------------------------------------------------ */
__global__ __launch_bounds__(128) void act_kernel(
    const float* __restrict__ A_log, const float* __restrict__ dt_bias,
    const float* __restrict__ Bnb, const float* __restrict__ Cnb)
{
    int row = blockIdx.x;
    float* pr = g_proj + (size_t)row * DP_;
    int tid = threadIdx.x, lane = tid & 31, w = tid >> 5;
    __shared__ float red[8];

    if (w == 0) {
        int h = lane;
        float xr = pr[6336 + h] + dt_bias[h];
        float sp = (xr > 20.f) ? xr : log1pf(expf(xr));
        float dt = fminf(fmaxf(sp, 1e-4f), 0.5f);
        float A = -expf(A_log[h]);
        float ldA = dt * A;
        float lam = 1.f / (1.f + expf(-pr[6368 + h]));
        g_logdA[row * 32 + h] = ldA;
        g_acoef[row * 32 + h] = lam * dt;
        g_bcoef[row * 32 + h] = (1.f - lam) * dt * expf(ldA);
        float s = dt;
#pragma unroll
        for (int o = 16; o > 0; o >>= 1) s += __shfl_xor_sync(0xffffffffu, s, o);
        float md = s * (1.f / 32.f);
        g_mt[row * 32 + h] = md * pr[6400 + h];
    }

    float bv = pr[6144 + tid];
    float ss = bv * bv;
#pragma unroll
    for (int o = 16; o > 0; o >>= 1) ss += __shfl_xor_sync(0xffffffffu, ss, o);
    if (lane == 0) red[w] = ss;
    __syncthreads();
    {
        int r = tid >> 6, n = tid & 63;
        float sum = red[r * 2] + red[r * 2 + 1];
        g_Bn[(size_t)row * 128 + tid] = bv * rsqrtf(sum * (1.f / 64.f) + EPS_F) * Bnb[n];
    }

    float cv = 0.f, ss2 = 0.f;
    if (tid < 64) {
        cv = pr[6272 + tid];
        ss2 = cv * cv;
#pragma unroll
        for (int o = 16; o > 0; o >>= 1) ss2 += __shfl_xor_sync(0xffffffffu, ss2, o);
        if (lane == 0) red[4 + w] = ss2;
    }
    __syncthreads();
    if (tid < 64) {
        float sum = red[4] + red[5];
        g_Cn[(size_t)row * 64 + tid] = cv * rsqrtf(sum * (1.f / 64.f) + EPS_F) * Cnb[tid];
    }

    for (int j = tid; j < 4096; j += 128) {
        float v = pr[2048 + j];
        pr[2048 + j] = v / (1.f + expf(-v));
    }
}

/* ------------------------------------------------------------------ */
/* 3. full-T inclusive scan of mean_dt*theta -> cos/sin of -cumsum     */
/* ------------------------------------------------------------------ */
__global__ __launch_bounds__(256) void scan_ang_kernel()
{
    int bk = blockIdx.x;
    int b = bk >> 5, k = bk & 31;
    int tid = threadIdx.x;
    size_t base = ((size_t)b * T_) * 32 + k;
    float v[8];
    float run = 0.f;
#pragma unroll
    for (int j = 0; j < 8; j++) {
        run += g_mt[base + (size_t)(tid * 8 + j) * 32];
        v[j] = run;
    }
    __shared__ float s[256];
    s[tid] = run;
    __syncthreads();
    for (int off = 1; off < 256; off <<= 1) {
        float xv = (tid >= off) ? s[tid - off] : 0.f;
        __syncthreads();
        s[tid] += xv;
        __syncthreads();
    }
    float excl = s[tid] - run;
#pragma unroll
    for (int j = 0; j < 8; j++) {
        float ang = -(excl + v[j]);
        size_t idx = base + (size_t)(tid * 8 + j) * 32;
        g_cosb[idx] = cosf(ang);
        g_sinb[idx] = sinf(ang);
    }
}

/* ------------------------------------------------------------------ */
/* 4. RoPE for C and B(r=0,1)                                          */
/* ------------------------------------------------------------------ */
__global__ __launch_bounds__(32) void rope_kernel()
{
    int row = blockIdx.x;
    int k = threadIdx.x;
    float cs = g_cosb[(size_t)row * 32 + k], sn = g_sinb[(size_t)row * 32 + k];
    float c1 = g_Cn[(size_t)row * 64 + k], c2 = g_Cn[(size_t)row * 64 + 32 + k];
    g_Cr[(size_t)row * 64 + k] = c1 * cs - c2 * sn;
    g_Cr[(size_t)row * 64 + 32 + k] = c1 * sn + c2 * cs;
#pragma unroll
    for (int r = 0; r < 2; r++) {
        float b1 = g_Bn[(size_t)row * 128 + r * 64 + k];
        float b2 = g_Bn[(size_t)row * 128 + r * 64 + 32 + k];
        g_Br[(size_t)row * 128 + r * 64 + k] = b1 * cs - b2 * sn;
        g_Br[(size_t)row * 128 + r * 64 + 32 + k] = b1 * sn + b2 * cs;
    }
}

/* ------------------------------------------------------------------ */
/* 5. within-chunk inclusive cumsum of log dA (smem-staged)            */
/* ------------------------------------------------------------------ */
__global__ __launch_bounds__(128) void cum_kernel()
{
    __shared__ float s[128 * 32];
    int blk = blockIdx.x;
    int tid = threadIdx.x;
    size_t base = (size_t)blk * 128 * 32;
    for (int i = tid; i < 4096; i += 128) s[i] = g_logdA[base + i];
    __syncthreads();
    if (tid < 32) {
        float run = 0.f;
        for (int l = 0; l < 128; l++) {
            run += s[l * 32 + tid];
            s[l * 32 + tid] = run;
        }
    }
    __syncthreads();
    for (int i = tid; i < 4096; i += 128) g_cum[base + i] = s[i];
}

/* ------------------------------------------------------------------ */
/* 5b. s_kernel: per (b,c) shared dot matrix                           */
/* ------------------------------------------------------------------ */
#define SC_STRIDE 69
#define SBS_STRIDE 133
#define SMEM_S_FLOATS (128*SC_STRIDE + 129*SBS_STRIDE)
__global__ __launch_bounds__(256) void s_kernel()
{
    extern __shared__ float sm[];
    float* sC = sm;
    float* sB = sm + 128 * SC_STRIDE;
    int c = blockIdx.x, b = blockIdx.y;
    int tid = threadIdx.x;
    int t0 = c * L_;
    size_t rb = (size_t)b * T_ + t0;

    for (int i = tid; i < 128 * 64; i += 256) {
        int l = i >> 6, n = i & 63;
        sC[l * SC_STRIDE + n] = g_Cr[(rb + l) * 64 + n];
    }
    for (int i = tid; i < 129 * 128; i += 256) {
        int row = i >> 7, j = i & 127;
        int t = t0 + row - 1;
        sB[row * SBS_STRIDE + j] = (t >= 0) ? g_Br[((size_t)b * T_ + t) * 128 + j] : 0.f;
    }
    __syncthreads();

    int lt = tid >> 3;
    int vg = tid & 7;
    float* gD = g_D + (size_t)(b * 16 + c) * 128 * 264;

#pragma unroll
    for (int pass = 0; pass < 5; pass++) {
        int v0 = pass * 64 + vg * 8;
        if (v0 < 258) {
            int boff[8];
#pragma unroll
            for (int u = 0; u < 8; u++) {
                int v = v0 + u; if (v > 257) v = 257;
                boff[u] = (v >> 1) * SBS_STRIDE + (v & 1) * 64;
            }
            float acc[4][8];
#pragma unroll
            for (int q = 0; q < 4; q++)
#pragma unroll
                for (int u = 0; u < 8; u++) acc[q][u] = 0.f;
            const float* cp = sC + (lt * 4) * SC_STRIDE;
            for (int k = 0; k < 64; k++) {
                float cv[4];
#pragma unroll
                for (int q = 0; q < 4; q++) cv[q] = cp[q * SC_STRIDE + k];
                float bv[8];
#pragma unroll
                for (int u = 0; u < 8; u++) bv[u] = sB[boff[u] + k];
#pragma unroll
                for (int q = 0; q < 4; q++)
#pragma unroll
                    for (int u = 0; u < 8; u++) acc[q][u] += cv[q] * bv[u];
            }
#pragma unroll
            for (int q = 0; q < 4; q++) {
                float* drow = gD + (size_t)(lt * 4 + q) * 264 + v0;
#pragma unroll
                for (int u = 0; u < 8; u++)
                    if (v0 + u < 258) drow[u] = acc[q][u];
            }
        }
    }
}

/* ------------------------------------------------------------------ */
/* 6. fused per-(b,c,h) chunk kernel: y_intra + chunk state st         */
/* R6 structure + register-carried d/x operands (LDS halving)          */
/* ------------------------------------------------------------------ */
#define SMEM_CHUNK_FLOATS 41224
__global__ __launch_bounds__(256) void chunk_kernel()
{
    extern __shared__ float sm[];
    float* sB   = sm;             /* 17028 */
    float* sX   = sm + 17028;     /* 17028 */
    float* sD   = sm + 34056;     /* 4608  */
    float* sDg  = sm + 38664;     /* 2048  */
    float* sCum = sm + 40712;     /* 128   */
    float* sA   = sm + 40840;     /* 128   */
    float* sBc  = sm + 40968;     /* 128   */
    float* sDE  = sm + 41096;     /* 128   */

    int h = blockIdx.x, c = blockIdx.y, b = blockIdx.z;
    int tid = threadIdx.x;
    int t0 = c * L_;
    size_t rb = (size_t)b * T_ + t0;
    const float* gD = g_D + (size_t)(b * 16 + c) * 128 * 264;

    for (int i = tid; i < 129 * 128; i += 256) {
        int row = i >> 7, j = i & 127;
        int t = t0 + row - 1;
        sB[row * 132 + j] = (t >= 0) ? g_Br[((size_t)b * T_ + t) * 128 + j] : 0.f;
    }
    for (int i = tid; i < 129 * 128; i += 256) {
        int row = i >> 7, j = i & 127;
        int t = t0 + row - 1;
        sX[row * 132 + j] = (t >= 0)
            ? g_proj[((size_t)b * T_ + t) * DP_ + 2048 + h * 128 + j] : 0.f;
    }
    if (tid < 128) {
        size_t g = (rb + tid) * 32 + h;
        sCum[tid] = g_cum[g];
        sA[tid] = g_acoef[g];
        sBc[tid] = g_bcoef[g];
    }
    __syncthreads();
    if (tid < 128) sDE[tid] = expf(sCum[127] - sCum[tid]);

    float acc[8][4];
#pragma unroll
    for (int i = 0; i < 8; i++)
#pragma unroll
        for (int q = 0; q < 4; q++) acc[i][q] = 0.f;

    int pg = tid & 15, p0 = pg << 2, lg = tid >> 4;

    for (int m0 = 0; m0 < 128; m0 += 16) {
        /* stage A': load shared dot tile from global */
        for (int e = tid; e < 4352; e += 256) {
            int l = e / 34;
            int rem = e - l * 34;
            sD[l * 36 + rem] = gD[(size_t)l * 264 + m0 * 2 + rem];
        }
        /* decay matrix tile */
        for (int e = tid; e < 2048; e += 256) {
            int l = e >> 4, mm = e & 15;
            int m = m0 + mm;
            sDg[e] = (m <= l) ? expf(sCum[l] - sCum[m]) : 0.f;
        }
        __syncthreads();

        /* preload carry registers */
        float d0x[8], d0y[8];
#pragma unroll
        for (int jl = 0; jl < 8; jl++) {
            int l = lg + (jl << 4);
            float2 dv = *(const float2*)&sD[l * 36];
            d0x[jl] = dv.x; d0y[jl] = dv.y;
        }
        float4 xba = *(const float4*)&sX[m0 * 132 + p0];
        float4 xbb = *(const float4*)&sX[m0 * 132 + 64 + p0];

        /* stage B: accumulate y with register-carried operands */
        for (int mm = 0; mm < 16; mm++) {
            int m = m0 + mm;
            float ea = sA[m], eb = sBc[m];
            float4 xga = *(const float4*)&sX[(m + 1) * 132 + p0];
            float4 xgb = *(const float4*)&sX[(m + 1) * 132 + 64 + p0];
            float xg0[4] = {ea * xga.x, ea * xga.y, ea * xga.z, ea * xga.w};
            float xg1[4] = {ea * xgb.x, ea * xgb.y, ea * xgb.z, ea * xgb.w};
            float xb0[4] = {eb * xba.x, eb * xba.y, eb * xba.z, eb * xba.w};
            float xb1[4] = {eb * xbb.x, eb * xbb.y, eb * xbb.z, eb * xbb.w};
            float d1x[8], d1y[8];
#pragma unroll
            for (int jl = 0; jl < 8; jl++) {
                int l = lg + (jl << 4);
                float2 dv = *(const float2*)&sD[l * 36 + (mm + 1) * 2];
                d1x[jl] = dv.x; d1y[jl] = dv.y;
                float gc = sDg[l * 16 + mm] * SCALE_F;
#pragma unroll
                for (int q = 0; q < 4; q++) {
                    float tq = d1x[jl] * xg0[q] + d1y[jl] * xg1[q]
                             + d0x[jl] * xb0[q] + d0y[jl] * xb1[q];
                    acc[jl][q] += gc * tq;
                }
            }
#pragma unroll
            for (int jl = 0; jl < 8; jl++) { d0x[jl] = d1x[jl]; d0y[jl] = d1y[jl]; }
            xba = xga; xbb = xgb;
        }
        __syncthreads();
    }
#pragma unroll
    for (int jl = 0; jl < 8; jl++) {
        int l = lg + (jl << 4);
        float4 outv = make_float4(acc[jl][0], acc[jl][1], acc[jl][2], acc[jl][3]);
        *(float4*)&g_y[(rb + l) * (size_t)DI_ + h * 64 + p0] = outv;
    }

    /* chunk state st[n][p] with carried x scalars */
    int p = tid & 63, ng = tid >> 6;
    float st[16];
#pragma unroll
    for (int jn = 0; jn < 16; jn++) st[jn] = 0.f;
    float xprev0 = sX[p], xprev1 = sX[64 + p];   /* row 0 */
    for (int m = 0; m < 128; m++) {
        float e = sDE[m];
        float eg = e * sA[m], ebk = e * sBc[m];
        float xnext0 = sX[(m + 1) * 132 + p];
        float xnext1 = sX[(m + 1) * 132 + 64 + p];
        float xg0 = eg * xnext0;
        float xg1 = eg * xnext1;
        float xb0 = ebk * xprev0;
        float xb1 = ebk * xprev1;
        const float* bg = &sB[(m + 1) * 132];
        const float* bb = &sB[m * 132];
#pragma unroll
        for (int jn = 0; jn < 16; jn++) {
            int n = ng * 16 + jn;
            st[jn] += bg[n] * xg0 + bg[64 + n] * xg1 + bb[n] * xb0 + bb[64 + n] * xb1;
        }
        xprev0 = xnext0; xprev1 = xnext1;
    }
    size_t so = (((size_t)(b * 16 + c) * 32 + h) * 4096);
#pragma unroll
    for (int jn = 0; jn < 16; jn++)
        g_st[so + (size_t)(ng * 16 + jn) * 64 + p] = st[jn];
}

/* ------------------------------------------------------------------ */
/* 7. inter-chunk state scan (16 steps)                                */
/* ------------------------------------------------------------------ */
__global__ __launch_bounds__(256) void scan_chunks_kernel()
{
    int b = blockIdx.x >> 5, h = blockIdx.x & 31;
    int tid = threadIdx.x;
    float S[16];
#pragma unroll
    for (int j = 0; j < 16; j++) S[j] = 0.f;
    for (int c = 0; c < 16; c++) {
        float cdec = expf(g_cum[((size_t)(b * 2048 + c * 128 + 127)) * 32 + h]);
        size_t off0 = (((size_t)(b * 16 + c) * 32 + h) * 4096);
#pragma unroll
        for (int j = 0; j < 16; j++) {
            size_t off = off0 + tid + j * 256;
            g_Sprev[off] = S[j];
            S[j] = cdec * S[j] + g_st[off];
        }
    }
}

/* ------------------------------------------------------------------ */
/* 8. y += SCALE * dec_in * (C @ Sprev)                                */
/* ------------------------------------------------------------------ */
#define SMEM_INTER_FLOATS (64*68 + 128*68 + 128)
__global__ __launch_bounds__(256) void inter_kernel()
{
    extern __shared__ float sm[];
    float* sS = sm;
    float* sC = sm + 64 * 68;
    float* sDec = sC + 128 * 68;
    int h = blockIdx.x, c = blockIdx.y, b = blockIdx.z;
    int tid = threadIdx.x;
    int t0 = c * 128;
    size_t rb = (size_t)b * T_ + t0;
    size_t soff = (((size_t)(b * 16 + c) * 32 + h) * 4096);

    for (int i = tid; i < 4096; i += 256)
        sS[(i >> 6) * 68 + (i & 63)] = g_Sprev[soff + i];
    for (int i = tid; i < 128 * 64; i += 256) {
        int l = i >> 6, n = i & 63;
        sC[l * 68 + n] = g_Cr[(rb + l) * 64 + n];
    }
    if (tid < 128) sDec[tid] = expf(g_cum[(rb + tid) * 32 + h]);
    __syncthreads();

    int pg = tid & 15, p0 = pg << 2, lg = tid >> 4;
#pragma unroll
    for (int jl = 0; jl < 8; jl++) {
        int l = lg + (jl << 4);
        float a0 = 0.f, a1 = 0.f, a2 = 0.f, a3 = 0.f;
#pragma unroll
        for (int n = 0; n < 64; n++) {
            float cv = sC[l * 68 + n];
            const float* sp = &sS[n * 68 + p0];
            a0 += cv * sp[0]; a1 += cv * sp[1];
            a2 += cv * sp[2]; a3 += cv * sp[3];
        }
        float coef = SCALE_F * sDec[l];
        float* yp = &g_y[(rb + l) * (size_t)DI_ + h * 64 + p0];
        yp[0] += coef * a0; yp[1] += coef * a1;
        yp[2] += coef * a2; yp[3] += coef * a3;
    }
}

/* ------------------------------------------------------------------ */
/* 9. y = rms(y * silu(z))                                             */
/* ------------------------------------------------------------------ */
__global__ __launch_bounds__(256) void gate_kernel()
{
    int row = blockIdx.x;
    int tid = threadIdx.x, lane = tid & 31, w = tid >> 5;
    const float* z = g_proj + (size_t)row * DP_;
    float* y = g_y + (size_t)row * DI_;
    float v[8];
    float ss = 0.f;
#pragma unroll
    for (int j = 0; j < 8; j++) {
        int i = tid + j * 256;
        float zv = z[i];
        float sz = zv / (1.f + expf(-zv));
        float vv = y[i] * sz;
        v[j] = vv;
        ss += vv * vv;
    }
#pragma unroll
    for (int o = 16; o > 0; o >>= 1) ss += __shfl_xor_sync(0xffffffffu, ss, o);
    __shared__ float red[8];
    if (lane == 0) red[w] = ss;
    __syncthreads();
    float tot = red[0] + red[1] + red[2] + red[3] + red[4] + red[5] + red[6] + red[7];
    float rinv = rsqrtf(tot * (1.f / 2048.f) + EPS_F);
#pragma unroll
    for (int j = 0; j < 8; j++) y[tid + j * 256] = v[j] * rinv;
}

/* ------------------------------------------------------------------ */
extern "C" void kernel_launch(void* const* d_in, const int* in_sizes, int n_in,
                              void* d_out, int out_size)
{
    const float* x       = (const float*)d_in[0];
    const float* W_in    = (const float*)d_in[1];
    const float* A_log   = (const float*)d_in[2];
    const float* dt_bias = (const float*)d_in[3];
    const float* Bnb     = (const float*)d_in[4];
    const float* Cnb     = (const float*)d_in[5];
    const float* W_out   = (const float*)d_in[6];
    float* out = (float*)d_out;

    void *p_proj = 0, *p_y = 0;
    cudaGetSymbolAddress(&p_proj, g_proj);
    cudaGetSymbolAddress(&p_y, g_y);

    cudaFuncSetAttribute(gemm_bf16x3, cudaFuncAttributeMaxDynamicSharedMemorySize,
                         GEMM_SMEM_BYTES);
    cudaFuncSetAttribute(s_kernel, cudaFuncAttributeMaxDynamicSharedMemorySize,
                         SMEM_S_FLOATS * 4);
    cudaFuncSetAttribute(chunk_kernel, cudaFuncAttributeMaxDynamicSharedMemorySize,
                         SMEM_CHUNK_FLOATS * 4);
    cudaFuncSetAttribute(inter_kernel, cudaFuncAttributeMaxDynamicSharedMemorySize,
                         SMEM_INTER_FLOATS * 4);

    /* 1. in-proj */
    gemm_bf16x3<<<dim3((DP_ + 127) / 128, RB_ / 128), 256, GEMM_SMEM_BYTES>>>(
        x, W_in, (float*)p_proj, RB_, DP_, DM_);
    /* 2. activations */
    act_kernel<<<RB_, 128>>>(A_log, dt_bias, Bnb, Cnb);
    /* 3. angle scan */
    scan_ang_kernel<<<B_ * 32, 256>>>();
    /* 4. rope */
    rope_kernel<<<RB_, 32>>>();
    /* 5. chunk cumsum */
    cum_kernel<<<B_ * NC_, 128>>>();
    /* 5b. shared dot matrix */
    s_kernel<<<dim3(NC_, B_), 256, SMEM_S_FLOATS * 4>>>();
    /* 6. fused chunk */
    chunk_kernel<<<dim3(H_, NC_, B_), 256, SMEM_CHUNK_FLOATS * 4>>>();
    /* 7. state scan */
    scan_chunks_kernel<<<B_ * H_, 256>>>();
    /* 8. inter */
    inter_kernel<<<dim3(H_, NC_, B_), 256, SMEM_INTER_FLOATS * 4>>>();
    /* 9. gate + rms */
    gate_kernel<<<RB_, 256>>>();
    /* 10. out-proj */
    gemm_bf16x3<<<dim3(DM_ / 128, RB_ / 128), 256, GEMM_SMEM_BYTES>>>(
        (const float*)p_y, W_out, out, RB_, DM_, DI_);
}

// round 12
// speedup vs baseline: 1.0527x; 1.0210x over previous
#include <cuda_runtime.h>
#include <math.h>
#include <stdint.h>

#define B_   2
#define T_   2048
#define DM_  1024
#define DP_  6432
#define DI_  2048
#define H_   32
#define P_   64
#define N_   64
#define L_   128
#define NC_  16
#define RB_  (B_*T_)          /* 4096 rows */
#define SCALE_F 0.08838834764831845f  /* 1/sqrt(128) */
#define EPS_F 1e-6f

/* ------------------------------------------------------------------ */
/* scratch (static device globals: allocation-free, graph-safe)        */
/* ------------------------------------------------------------------ */
__device__ float g_proj[(size_t)RB_ * DP_];       /* 105 MB */
__device__ float g_logdA[RB_ * H_];
__device__ float g_acoef[RB_ * H_];
__device__ float g_bcoef[RB_ * H_];
__device__ float g_mt[RB_ * H_];
__device__ float g_cosb[RB_ * H_];
__device__ float g_sinb[RB_ * H_];
__device__ float g_cum[RB_ * H_];
__device__ float g_Bn[RB_ * 128];
__device__ float g_Cn[RB_ * 64];
__device__ float g_Br[RB_ * 128];
__device__ float g_Cr[RB_ * 64];
__device__ float g_st[(size_t)B_ * NC_ * H_ * N_ * P_];
__device__ float g_Sprev[(size_t)B_ * NC_ * H_ * N_ * P_];
__device__ float g_y[(size_t)RB_ * DI_];
/* shared (head-independent) C.B dot matrix: [b*16+c][l:128][v:258 pad 264] */
__device__ float g_D[(size_t)B_ * NC_ * 128 * 264];

/* ------------------------------------------------------------------ */
/* bf16x3 tensor-core GEMM (R6 version: convert-in-smem).              */
/* ------------------------------------------------------------------ */
#define AST_STRIDE 36
#define BST_STRIDE 132
#define AST_SIZE (128*AST_STRIDE)
#define BST_SIZE (32*BST_STRIDE)
#define AP_STRIDE 20
#define BP_STRIDE 136
#define AP_SIZE  (128*AP_STRIDE)
#define BP_SIZE  (16*BP_STRIDE)
#define OFF_AST  0
#define OFF_BST  (2*AST_SIZE)
#define OFF_AH   (OFF_BST + 2*BST_SIZE)
#define OFF_AL   (OFF_AH + AP_SIZE)
#define OFF_BH   (OFF_AL + AP_SIZE)
#define OFF_BL   (OFF_BH + BP_SIZE)
#define GEMM_WORDS (OFF_BL + BP_SIZE)
#define GEMM_SMEM_BYTES (GEMM_WORDS * 4)

__device__ __forceinline__ uint32_t smem_u32(const void* p) {
    return (uint32_t)__cvta_generic_to_shared(p);
}
__device__ __forceinline__ void cp16(uint32_t dst, const void* src, int pred_bytes) {
    asm volatile("cp.async.cg.shared.global [%0], [%1], 16, %2;"
                 :: "r"(dst), "l"(src), "r"(pred_bytes));
}
__device__ __forceinline__ void f2bf2(float x0, float x1, uint32_t& h, uint32_t& l) {
    asm("cvt.rn.bf16x2.f32 %0, %1, %2;" : "=r"(h) : "f"(x1), "f"(x0));
    float h0 = __uint_as_float(h << 16);
    float h1 = __uint_as_float(h & 0xffff0000u);
    float l0 = x0 - h0, l1 = x1 - h1;
    asm("cvt.rn.bf16x2.f32 %0, %1, %2;" : "=r"(l) : "f"(l1), "f"(l0));
}
__device__ __forceinline__ void mma16(float* c, const uint32_t* a, const uint32_t* b) {
    asm volatile(
        "mma.sync.aligned.m16n8k16.row.col.f32.bf16.bf16.f32 "
        "{%0,%1,%2,%3}, {%4,%5,%6,%7}, {%8,%9}, {%0,%1,%2,%3};"
        : "+f"(c[0]), "+f"(c[1]), "+f"(c[2]), "+f"(c[3])
        : "r"(a[0]), "r"(a[1]), "r"(a[2]), "r"(a[3]), "r"(b[0]), "r"(b[1]));
}

__global__ __launch_bounds__(256, 2) void gemm_bf16x3(
    const float* __restrict__ A, const float* __restrict__ Bm,
    float* __restrict__ C, int M, int N, int K)
{
    extern __shared__ float sm[];
    float* ASt = sm + OFF_AST;
    float* BSt = sm + OFF_BST;
    uint32_t* Ah = (uint32_t*)(sm + OFF_AH);
    uint32_t* Al = (uint32_t*)(sm + OFF_AL);
    uint32_t* Bh = (uint32_t*)(sm + OFF_BH);
    uint32_t* Bl = (uint32_t*)(sm + OFF_BL);

    int tid = threadIdx.x;
    int bm = blockIdx.y * 128, bn = blockIdx.x * 128;
    int warp = tid >> 5, lane = tid & 31;
    int gid = lane >> 2, tig = lane & 3;
    int wm = (warp & 1) * 64;
    int wn = (warp >> 1) * 32;

    float acc[4][4][4];
#pragma unroll
    for (int mt = 0; mt < 4; mt++)
#pragma unroll
        for (int nt = 0; nt < 4; nt++)
#pragma unroll
            for (int q = 0; q < 4; q++) acc[mt][nt][q] = 0.f;

    int KTn = K >> 5;

#define PREFETCH(ktv, buf)                                                      \
    {                                                                           \
        int k0 = (ktv) << 5;                                                    \
        float* Ab_ = ASt + (buf) * AST_SIZE;                                    \
        float* Bb_ = BSt + (buf) * BST_SIZE;                                    \
        _Pragma("unroll")                                                       \
        for (int i = 0; i < 4; i++) {                                           \
            int idx = tid + i * 256;                                            \
            int row = idx >> 3, kc = (idx & 7) << 2;                            \
            cp16(smem_u32(&Ab_[row * AST_STRIDE + kc]),                         \
                 A + (size_t)(bm + row) * K + k0 + kc, 16);                     \
        }                                                                       \
        _Pragma("unroll")                                                       \
        for (int i = 0; i < 4; i++) {                                           \
            int idx = tid + i * 256;                                            \
            int row = idx >> 5, nc = (idx & 31) << 2;                           \
            int ok = (bn + nc) < N;                                             \
            const float* src = ok ? (Bm + (size_t)(k0 + row) * N + bn + nc) : Bm; \
            cp16(smem_u32(&Bb_[row * BST_STRIDE + nc]), src, ok ? 16 : 0);      \
        }                                                                       \
        asm volatile("cp.async.commit_group;");                                 \
    }

    PREFETCH(0, 0);

    for (int kt = 0; kt < KTn; kt++) {
        if (kt + 1 < KTn) {
            PREFETCH(kt + 1, (kt + 1) & 1);
            asm volatile("cp.async.wait_group 1;");
        } else {
            asm volatile("cp.async.wait_group 0;");
        }
        __syncthreads();

        {
            const float* Ab = ASt + (kt & 1) * AST_SIZE;
            const float* Bb = BSt + (kt & 1) * BST_SIZE;
            int mq = tid >> 4, kpA = tid & 15;
#pragma unroll
            for (int j = 0; j < 8; j++) {
                int m = j * 16 + mq;
                float2 v = *(const float2*)&Ab[m * AST_STRIDE + 2 * kpA];
                uint32_t hh, ll;
                f2bf2(v.x, v.y, hh, ll);
                Ah[m * AP_STRIDE + kpA] = hh;
                Al[m * AP_STRIDE + kpA] = ll;
            }
            int n = tid & 127, kq = tid >> 7;
#pragma unroll
            for (int j = 0; j < 8; j++) {
                int kp = j * 2 + kq;
                float b0 = Bb[(2 * kp) * BST_STRIDE + n];
                float b1 = Bb[(2 * kp + 1) * BST_STRIDE + n];
                uint32_t hh, ll;
                f2bf2(b0, b1, hh, ll);
                Bh[kp * BP_STRIDE + n] = hh;
                Bl[kp * BP_STRIDE + n] = ll;
            }
        }
        __syncthreads();

#pragma unroll
        for (int ks = 0; ks < 2; ks++) {
            int kp0 = ks * 8 + tig;
            uint32_t bh[4][2], bl[4][2];
#pragma unroll
            for (int nt = 0; nt < 4; nt++) {
                int n = wn + nt * 8 + gid;
                bh[nt][0] = Bh[kp0 * BP_STRIDE + n];
                bh[nt][1] = Bh[(kp0 + 4) * BP_STRIDE + n];
                bl[nt][0] = Bl[kp0 * BP_STRIDE + n];
                bl[nt][1] = Bl[(kp0 + 4) * BP_STRIDE + n];
            }
#pragma unroll
            for (int mt = 0; mt < 4; mt++) {
                int m0 = wm + mt * 16 + gid;
                uint32_t ah[4], al[4];
                ah[0] = Ah[m0 * AP_STRIDE + kp0];
                ah[1] = Ah[(m0 + 8) * AP_STRIDE + kp0];
                ah[2] = Ah[m0 * AP_STRIDE + kp0 + 4];
                ah[3] = Ah[(m0 + 8) * AP_STRIDE + kp0 + 4];
                al[0] = Al[m0 * AP_STRIDE + kp0];
                al[1] = Al[(m0 + 8) * AP_STRIDE + kp0];
                al[2] = Al[m0 * AP_STRIDE + kp0 + 4];
                al[3] = Al[(m0 + 8) * AP_STRIDE + kp0 + 4];
#pragma unroll
                for (int nt = 0; nt < 4; nt++) {
                    mma16(acc[mt][nt], ah, bh[nt]);
                    mma16(acc[mt][nt], al, bh[nt]);
                    mma16(acc[mt][nt], ah, bl[nt]);
                }
            }
        }
        __syncthreads();
    }

#pragma unroll
    for (int mt = 0; mt < 4; mt++) {
#pragma unroll
        for (int nt = 0; nt < 4; nt++) {
            int row0 = bm + wm + mt * 16 + gid;
            int col = bn + wn + nt * 8 + tig * 2;
            if (col < N) {
                *(float2*)&C[(size_t)row0 * N + col] =
                    make_float2(acc[mt][nt][0], acc[mt][nt][1]);
                *(float2*)&C[(size_t)(row0 + 8) * N + col] =
                    make_float2(acc[mt][nt][2], acc[mt][nt][3]);
            }
        }
    }
}

/* ------------------------------------------------------------------ */
/* 2. per-(b,t): dt/lambda/alpha + coefs, RMS of B/C, silu(x), mt      */
/* ------------------------------------------------------------------ */
__global__ __launch_bounds__(128) void act_kernel(
    const float* __restrict__ A_log, const float* __restrict__ dt_bias,
    const float* __restrict__ Bnb, const float* __restrict__ Cnb)
{
    int row = blockIdx.x;
    float* pr = g_proj + (size_t)row * DP_;
    int tid = threadIdx.x, lane = tid & 31, w = tid >> 5;
    __shared__ float red[8];

    if (w == 0) {
        int h = lane;
        float xr = pr[6336 + h] + dt_bias[h];
        float sp = (xr > 20.f) ? xr : log1pf(expf(xr));
        float dt = fminf(fmaxf(sp, 1e-4f), 0.5f);
        float A = -expf(A_log[h]);
        float ldA = dt * A;
        float lam = 1.f / (1.f + expf(-pr[6368 + h]));
        g_logdA[row * 32 + h] = ldA;
        g_acoef[row * 32 + h] = lam * dt;
        g_bcoef[row * 32 + h] = (1.f - lam) * dt * expf(ldA);
        float s = dt;
#pragma unroll
        for (int o = 16; o > 0; o >>= 1) s += __shfl_xor_sync(0xffffffffu, s, o);
        float md = s * (1.f / 32.f);
        g_mt[row * 32 + h] = md * pr[6400 + h];
    }

    float bv = pr[6144 + tid];
    float ss = bv * bv;
#pragma unroll
    for (int o = 16; o > 0; o >>= 1) ss += __shfl_xor_sync(0xffffffffu, ss, o);
    if (lane == 0) red[w] = ss;
    __syncthreads();
    {
        int r = tid >> 6, n = tid & 63;
        float sum = red[r * 2] + red[r * 2 + 1];
        g_Bn[(size_t)row * 128 + tid] = bv * rsqrtf(sum * (1.f / 64.f) + EPS_F) * Bnb[n];
    }

    float cv = 0.f, ss2 = 0.f;
    if (tid < 64) {
        cv = pr[6272 + tid];
        ss2 = cv * cv;
#pragma unroll
        for (int o = 16; o > 0; o >>= 1) ss2 += __shfl_xor_sync(0xffffffffu, ss2, o);
        if (lane == 0) red[4 + w] = ss2;
    }
    __syncthreads();
    if (tid < 64) {
        float sum = red[4] + red[5];
        g_Cn[(size_t)row * 64 + tid] = cv * rsqrtf(sum * (1.f / 64.f) + EPS_F) * Cnb[tid];
    }

    for (int j = tid; j < 4096; j += 128) {
        float v = pr[2048 + j];
        pr[2048 + j] = v / (1.f + expf(-v));
    }
}

/* ------------------------------------------------------------------ */
/* 3. full-T inclusive scan of mean_dt*theta -> cos/sin of -cumsum     */
/* ------------------------------------------------------------------ */
__global__ __launch_bounds__(256) void scan_ang_kernel()
{
    int bk = blockIdx.x;
    int b = bk >> 5, k = bk & 31;
    int tid = threadIdx.x;
    size_t base = ((size_t)b * T_) * 32 + k;
    float v[8];
    float run = 0.f;
#pragma unroll
    for (int j = 0; j < 8; j++) {
        run += g_mt[base + (size_t)(tid * 8 + j) * 32];
        v[j] = run;
    }
    __shared__ float s[256];
    s[tid] = run;
    __syncthreads();
    for (int off = 1; off < 256; off <<= 1) {
        float xv = (tid >= off) ? s[tid - off] : 0.f;
        __syncthreads();
        s[tid] += xv;
        __syncthreads();
    }
    float excl = s[tid] - run;
#pragma unroll
    for (int j = 0; j < 8; j++) {
        float ang = -(excl + v[j]);
        size_t idx = base + (size_t)(tid * 8 + j) * 32;
        g_cosb[idx] = cosf(ang);
        g_sinb[idx] = sinf(ang);
    }
}

/* ------------------------------------------------------------------ */
/* 4. RoPE for C and B(r=0,1)                                          */
/* ------------------------------------------------------------------ */
__global__ __launch_bounds__(32) void rope_kernel()
{
    int row = blockIdx.x;
    int k = threadIdx.x;
    float cs = g_cosb[(size_t)row * 32 + k], sn = g_sinb[(size_t)row * 32 + k];
    float c1 = g_Cn[(size_t)row * 64 + k], c2 = g_Cn[(size_t)row * 64 + 32 + k];
    g_Cr[(size_t)row * 64 + k] = c1 * cs - c2 * sn;
    g_Cr[(size_t)row * 64 + 32 + k] = c1 * sn + c2 * cs;
#pragma unroll
    for (int r = 0; r < 2; r++) {
        float b1 = g_Bn[(size_t)row * 128 + r * 64 + k];
        float b2 = g_Bn[(size_t)row * 128 + r * 64 + 32 + k];
        g_Br[(size_t)row * 128 + r * 64 + k] = b1 * cs - b2 * sn;
        g_Br[(size_t)row * 128 + r * 64 + 32 + k] = b1 * sn + b2 * cs;
    }
}

/* ------------------------------------------------------------------ */
/* 5. within-chunk inclusive cumsum of log dA (smem-staged)            */
/* ------------------------------------------------------------------ */
__global__ __launch_bounds__(128) void cum_kernel()
{
    __shared__ float s[128 * 32];
    int blk = blockIdx.x;
    int tid = threadIdx.x;
    size_t base = (size_t)blk * 128 * 32;
    for (int i = tid; i < 4096; i += 128) s[i] = g_logdA[base + i];
    __syncthreads();
    if (tid < 32) {
        float run = 0.f;
        for (int l = 0; l < 128; l++) {
            run += s[l * 32 + tid];
            s[l * 32 + tid] = run;
        }
    }
    __syncthreads();
    for (int i = tid; i < 4096; i += 128) g_cum[base + i] = s[i];
}

/* ------------------------------------------------------------------ */
/* 5b. s_kernel: per (b,c) shared dot matrix                           */
/* ------------------------------------------------------------------ */
#define SC_STRIDE 69
#define SBS_STRIDE 133
#define SMEM_S_FLOATS (128*SC_STRIDE + 129*SBS_STRIDE)
__global__ __launch_bounds__(256) void s_kernel()
{
    extern __shared__ float sm[];
    float* sC = sm;
    float* sB = sm + 128 * SC_STRIDE;
    int c = blockIdx.x, b = blockIdx.y;
    int tid = threadIdx.x;
    int t0 = c * L_;
    size_t rb = (size_t)b * T_ + t0;

    for (int i = tid; i < 128 * 64; i += 256) {
        int l = i >> 6, n = i & 63;
        sC[l * SC_STRIDE + n] = g_Cr[(rb + l) * 64 + n];
    }
    for (int i = tid; i < 129 * 128; i += 256) {
        int row = i >> 7, j = i & 127;
        int t = t0 + row - 1;
        sB[row * SBS_STRIDE + j] = (t >= 0) ? g_Br[((size_t)b * T_ + t) * 128 + j] : 0.f;
    }
    __syncthreads();

    int lt = tid >> 3;
    int vg = tid & 7;
    float* gD = g_D + (size_t)(b * 16 + c) * 128 * 264;

#pragma unroll
    for (int pass = 0; pass < 5; pass++) {
        int v0 = pass * 64 + vg * 8;
        if (v0 < 258) {
            int boff[8];
#pragma unroll
            for (int u = 0; u < 8; u++) {
                int v = v0 + u; if (v > 257) v = 257;
                boff[u] = (v >> 1) * SBS_STRIDE + (v & 1) * 64;
            }
            float acc[4][8];
#pragma unroll
            for (int q = 0; q < 4; q++)
#pragma unroll
                for (int u = 0; u < 8; u++) acc[q][u] = 0.f;
            const float* cp = sC + (lt * 4) * SC_STRIDE;
            for (int k = 0; k < 64; k++) {
                float cv[4];
#pragma unroll
                for (int q = 0; q < 4; q++) cv[q] = cp[q * SC_STRIDE + k];
                float bv[8];
#pragma unroll
                for (int u = 0; u < 8; u++) bv[u] = sB[boff[u] + k];
#pragma unroll
                for (int q = 0; q < 4; q++)
#pragma unroll
                    for (int u = 0; u < 8; u++) acc[q][u] += cv[q] * bv[u];
            }
#pragma unroll
            for (int q = 0; q < 4; q++) {
                float* drow = gD + (size_t)(lt * 4 + q) * 264 + v0;
#pragma unroll
                for (int u = 0; u < 8; u++)
                    if (v0 + u < 258) drow[u] = acc[q][u];
            }
        }
    }
}

/* ------------------------------------------------------------------ */
/* 6. fused per-(b,c,h) chunk kernel: y_intra + chunk state st         */
/* compile-time causal tile skip (m0 loop fully unrolled)              */
/* ------------------------------------------------------------------ */
#define SMEM_CHUNK_FLOATS 41224
__global__ __launch_bounds__(256) void chunk_kernel()
{
    extern __shared__ float sm[];
    float* sB   = sm;             /* 17028 */
    float* sX   = sm + 17028;     /* 17028 */
    float* sD   = sm + 34056;     /* 4608  */
    float* sDg  = sm + 38664;     /* 2048  */
    float* sCum = sm + 40712;     /* 128   */
    float* sA   = sm + 40840;     /* 128   */
    float* sBc  = sm + 40968;     /* 128   */
    float* sDE  = sm + 41096;     /* 128   */

    int h = blockIdx.x, c = blockIdx.y, b = blockIdx.z;
    int tid = threadIdx.x;
    int t0 = c * L_;
    size_t rb = (size_t)b * T_ + t0;
    const float* gD = g_D + (size_t)(b * 16 + c) * 128 * 264;

    for (int i = tid; i < 129 * 128; i += 256) {
        int row = i >> 7, j = i & 127;
        int t = t0 + row - 1;
        sB[row * 132 + j] = (t >= 0) ? g_Br[((size_t)b * T_ + t) * 128 + j] : 0.f;
    }
    for (int i = tid; i < 129 * 128; i += 256) {
        int row = i >> 7, j = i & 127;
        int t = t0 + row - 1;
        sX[row * 132 + j] = (t >= 0)
            ? g_proj[((size_t)b * T_ + t) * DP_ + 2048 + h * 128 + j] : 0.f;
    }
    if (tid < 128) {
        size_t g = (rb + tid) * 32 + h;
        sCum[tid] = g_cum[g];
        sA[tid] = g_acoef[g];
        sBc[tid] = g_bcoef[g];
    }
    __syncthreads();
    if (tid < 128) sDE[tid] = expf(sCum[127] - sCum[tid]);

    float acc[8][4];
#pragma unroll
    for (int i = 0; i < 8; i++)
#pragma unroll
        for (int q = 0; q < 4; q++) acc[i][q] = 0.f;

    int pg = tid & 15, p0 = pg << 2, lg = tid >> 4;

#pragma unroll
    for (int m0t = 0; m0t < 8; m0t++) {
        const int m0 = m0t << 4;
        /* stage A': load shared dot tile rows l >= m0 (others unused) */
        for (int e = tid; e < (128 - m0) * 34; e += 256) {
            int lr = e / 34;
            int rem = e - lr * 34;
            int l = m0 + lr;
            sD[l * 36 + rem] = gD[(size_t)l * 264 + m0 * 2 + rem];
        }
        /* decay matrix tile rows l >= m0 (m0*16 is a multiple of 256) */
        for (int e = tid + m0 * 16; e < 2048; e += 256) {
            int l = e >> 4, mm = e & 15;
            int m = m0 + mm;
            sDg[e] = (m <= l) ? expf(sCum[l] - sCum[m]) : 0.f;
        }
        __syncthreads();

        /* preload carry registers for active tiles */
        float d0x[8], d0y[8];
#pragma unroll
        for (int jl = 0; jl < 8; jl++) {
            if (jl >= m0t) {
                int l = lg + (jl << 4);
                float2 dv = *(const float2*)&sD[l * 36];
                d0x[jl] = dv.x; d0y[jl] = dv.y;
            } else { d0x[jl] = 0.f; d0y[jl] = 0.f; }
        }
        float4 xba = *(const float4*)&sX[m0 * 132 + p0];
        float4 xbb = *(const float4*)&sX[m0 * 132 + 64 + p0];

        for (int mm = 0; mm < 16; mm++) {
            int m = m0 + mm;
            float ea = sA[m], eb = sBc[m];
            float4 xga = *(const float4*)&sX[(m + 1) * 132 + p0];
            float4 xgb = *(const float4*)&sX[(m + 1) * 132 + 64 + p0];
            float xg0[4] = {ea * xga.x, ea * xga.y, ea * xga.z, ea * xga.w};
            float xg1[4] = {ea * xgb.x, ea * xgb.y, ea * xgb.z, ea * xgb.w};
            float xb0[4] = {eb * xba.x, eb * xba.y, eb * xba.z, eb * xba.w};
            float xb1[4] = {eb * xbb.x, eb * xbb.y, eb * xbb.z, eb * xbb.w};
            float d1x[8], d1y[8];
#pragma unroll
            for (int jl = 0; jl < 8; jl++) {
                if (jl >= m0t) {          /* compile-time: m0t const per unroll */
                    int l = lg + (jl << 4);
                    float2 dv = *(const float2*)&sD[l * 36 + (mm + 1) * 2];
                    d1x[jl] = dv.x; d1y[jl] = dv.y;
                    float gc = sDg[l * 16 + mm] * SCALE_F;
#pragma unroll
                    for (int q = 0; q < 4; q++) {
                        float tq = d1x[jl] * xg0[q] + d1y[jl] * xg1[q]
                                 + d0x[jl] * xb0[q] + d0y[jl] * xb1[q];
                        acc[jl][q] += gc * tq;
                    }
                }
            }
#pragma unroll
            for (int jl = 0; jl < 8; jl++) {
                if (jl >= m0t) { d0x[jl] = d1x[jl]; d0y[jl] = d1y[jl]; }
            }
            xba = xga; xbb = xgb;
        }
        __syncthreads();
    }
#pragma unroll
    for (int jl = 0; jl < 8; jl++) {
        int l = lg + (jl << 4);
        float4 outv = make_float4(acc[jl][0], acc[jl][1], acc[jl][2], acc[jl][3]);
        *(float4*)&g_y[(rb + l) * (size_t)DI_ + h * 64 + p0] = outv;
    }

    /* chunk state st[n][p] with carried x scalars */
    int p = tid & 63, ng = tid >> 6;
    float st[16];
#pragma unroll
    for (int jn = 0; jn < 16; jn++) st[jn] = 0.f;
    float xprev0 = sX[p], xprev1 = sX[64 + p];   /* row 0 */
    for (int m = 0; m < 128; m++) {
        float e = sDE[m];
        float eg = e * sA[m], ebk = e * sBc[m];
        float xnext0 = sX[(m + 1) * 132 + p];
        float xnext1 = sX[(m + 1) * 132 + 64 + p];
        float xg0 = eg * xnext0;
        float xg1 = eg * xnext1;
        float xb0 = ebk * xprev0;
        float xb1 = ebk * xprev1;
        const float* bg = &sB[(m + 1) * 132];
        const float* bb = &sB[m * 132];
#pragma unroll
        for (int jn = 0; jn < 16; jn++) {
            int n = ng * 16 + jn;
            st[jn] += bg[n] * xg0 + bg[64 + n] * xg1 + bb[n] * xb0 + bb[64 + n] * xb1;
        }
        xprev0 = xnext0; xprev1 = xnext1;
    }
    size_t so = (((size_t)(b * 16 + c) * 32 + h) * 4096);
#pragma unroll
    for (int jn = 0; jn < 16; jn++)
        g_st[so + (size_t)(ng * 16 + jn) * 64 + p] = st[jn];
}

/* ------------------------------------------------------------------ */
/* 7. inter-chunk state scan (16 steps)                                */
/* ------------------------------------------------------------------ */
__global__ __launch_bounds__(256) void scan_chunks_kernel()
{
    int b = blockIdx.x >> 5, h = blockIdx.x & 31;
    int tid = threadIdx.x;
    float S[16];
#pragma unroll
    for (int j = 0; j < 16; j++) S[j] = 0.f;
    for (int c = 0; c < 16; c++) {
        float cdec = expf(g_cum[((size_t)(b * 2048 + c * 128 + 127)) * 32 + h]);
        size_t off0 = (((size_t)(b * 16 + c) * 32 + h) * 4096);
#pragma unroll
        for (int j = 0; j < 16; j++) {
            size_t off = off0 + tid + j * 256;
            g_Sprev[off] = S[j];
            S[j] = cdec * S[j] + g_st[off];
        }
    }
}

/* ------------------------------------------------------------------ */
/* 8. y += SCALE * dec_in * (C @ Sprev)                                */
/* ------------------------------------------------------------------ */
#define SMEM_INTER_FLOATS (64*68 + 128*68 + 128)
__global__ __launch_bounds__(256) void inter_kernel()
{
    extern __shared__ float sm[];
    float* sS = sm;
    float* sC = sm + 64 * 68;
    float* sDec = sC + 128 * 68;
    int h = blockIdx.x, c = blockIdx.y, b = blockIdx.z;
    int tid = threadIdx.x;
    int t0 = c * 128;
    size_t rb = (size_t)b * T_ + t0;
    size_t soff = (((size_t)(b * 16 + c) * 32 + h) * 4096);

    for (int i = tid; i < 4096; i += 256)
        sS[(i >> 6) * 68 + (i & 63)] = g_Sprev[soff + i];
    for (int i = tid; i < 128 * 64; i += 256) {
        int l = i >> 6, n = i & 63;
        sC[l * 68 + n] = g_Cr[(rb + l) * 64 + n];
    }
    if (tid < 128) sDec[tid] = expf(g_cum[(rb + tid) * 32 + h]);
    __syncthreads();

    int pg = tid & 15, p0 = pg << 2, lg = tid >> 4;
#pragma unroll
    for (int jl = 0; jl < 8; jl++) {
        int l = lg + (jl << 4);
        float a0 = 0.f, a1 = 0.f, a2 = 0.f, a3 = 0.f;
#pragma unroll
        for (int n = 0; n < 64; n++) {
            float cv = sC[l * 68 + n];
            const float* sp = &sS[n * 68 + p0];
            a0 += cv * sp[0]; a1 += cv * sp[1];
            a2 += cv * sp[2]; a3 += cv * sp[3];
        }
        float coef = SCALE_F * sDec[l];
        float* yp = &g_y[(rb + l) * (size_t)DI_ + h * 64 + p0];
        yp[0] += coef * a0; yp[1] += coef * a1;
        yp[2] += coef * a2; yp[3] += coef * a3;
    }
}

/* ------------------------------------------------------------------ */
/* 9. y = rms(y * silu(z))                                             */
/* ------------------------------------------------------------------ */
__global__ __launch_bounds__(256) void gate_kernel()
{
    int row = blockIdx.x;
    int tid = threadIdx.x, lane = tid & 31, w = tid >> 5;
    const float* z = g_proj + (size_t)row * DP_;
    float* y = g_y + (size_t)row * DI_;
    float v[8];
    float ss = 0.f;
#pragma unroll
    for (int j = 0; j < 8; j++) {
        int i = tid + j * 256;
        float zv = z[i];
        float sz = zv / (1.f + expf(-zv));
        float vv = y[i] * sz;
        v[j] = vv;
        ss += vv * vv;
    }
#pragma unroll
    for (int o = 16; o > 0; o >>= 1) ss += __shfl_xor_sync(0xffffffffu, ss, o);
    __shared__ float red[8];
    if (lane == 0) red[w] = ss;
    __syncthreads();
    float tot = red[0] + red[1] + red[2] + red[3] + red[4] + red[5] + red[6] + red[7];
    float rinv = rsqrtf(tot * (1.f / 2048.f) + EPS_F);
#pragma unroll
    for (int j = 0; j < 8; j++) y[tid + j * 256] = v[j] * rinv;
}

/* ------------------------------------------------------------------ */
extern "C" void kernel_launch(void* const* d_in, const int* in_sizes, int n_in,
                              void* d_out, int out_size)
{
    const float* x       = (const float*)d_in[0];
    const float* W_in    = (const float*)d_in[1];
    const float* A_log   = (const float*)d_in[2];
    const float* dt_bias = (const float*)d_in[3];
    const float* Bnb     = (const float*)d_in[4];
    const float* Cnb     = (const float*)d_in[5];
    const float* W_out   = (const float*)d_in[6];
    float* out = (float*)d_out;

    void *p_proj = 0, *p_y = 0;
    cudaGetSymbolAddress(&p_proj, g_proj);
    cudaGetSymbolAddress(&p_y, g_y);

    cudaFuncSetAttribute(gemm_bf16x3, cudaFuncAttributeMaxDynamicSharedMemorySize,
                         GEMM_SMEM_BYTES);
    cudaFuncSetAttribute(s_kernel, cudaFuncAttributeMaxDynamicSharedMemorySize,
                         SMEM_S_FLOATS * 4);
    cudaFuncSetAttribute(chunk_kernel, cudaFuncAttributeMaxDynamicSharedMemorySize,
                         SMEM_CHUNK_FLOATS * 4);
    cudaFuncSetAttribute(inter_kernel, cudaFuncAttributeMaxDynamicSharedMemorySize,
                         SMEM_INTER_FLOATS * 4);

    /* 1. in-proj */
    gemm_bf16x3<<<dim3((DP_ + 127) / 128, RB_ / 128), 256, GEMM_SMEM_BYTES>>>(
        x, W_in, (float*)p_proj, RB_, DP_, DM_);
    /* 2. activations */
    act_kernel<<<RB_, 128>>>(A_log, dt_bias, Bnb, Cnb);
    /* 3. angle scan */
    scan_ang_kernel<<<B_ * 32, 256>>>();
    /* 4. rope */
    rope_kernel<<<RB_, 32>>>();
    /* 5. chunk cumsum */
    cum_kernel<<<B_ * NC_, 128>>>();
    /* 5b. shared dot matrix */
    s_kernel<<<dim3(NC_, B_), 256, SMEM_S_FLOATS * 4>>>();
    /* 6. fused chunk */
    chunk_kernel<<<dim3(H_, NC_, B_), 256, SMEM_CHUNK_FLOATS * 4>>>();
    /* 7. state scan */
    scan_chunks_kernel<<<B_ * H_, 256>>>();
    /* 8. inter */
    inter_kernel<<<dim3(H_, NC_, B_), 256, SMEM_INTER_FLOATS * 4>>>();
    /* 9. gate + rms */
    gate_kernel<<<RB_, 256>>>();
    /* 10. out-proj */
    gemm_bf16x3<<<dim3(DM_ / 128, RB_ / 128), 256, GEMM_SMEM_BYTES>>>(
        (const float*)p_y, W_out, out, RB_, DM_, DI_);
}

// round 13
// speedup vs baseline: 1.1501x; 1.0925x over previous
#include <cuda_runtime.h>
#include <math.h>
#include <stdint.h>

#define B_   2
#define T_   2048
#define DM_  1024
#define DP_  6432
#define DI_  2048
#define H_   32
#define P_   64
#define N_   64
#define L_   128
#define NC_  16
#define RB_  (B_*T_)          /* 4096 rows */
#define SCALE_F 0.08838834764831845f  /* 1/sqrt(128) */
#define EPS_F 1e-6f

/* ------------------------------------------------------------------ */
/* scratch (static device globals: allocation-free, graph-safe)        */
/* ------------------------------------------------------------------ */
__device__ float g_proj[(size_t)RB_ * DP_];       /* 105 MB */
__device__ float g_logdA[RB_ * H_];
__device__ float g_acoef[RB_ * H_];
__device__ float g_bcoef[RB_ * H_];
__device__ float g_mt[RB_ * H_];
__device__ float g_cosb[RB_ * H_];
__device__ float g_sinb[RB_ * H_];
__device__ float g_cum[RB_ * H_];
__device__ float g_Bn[RB_ * 128];
__device__ float g_Cn[RB_ * 64];
__device__ float g_Br[RB_ * 128];
__device__ float g_Cr[RB_ * 64];
__device__ float g_st[(size_t)B_ * NC_ * H_ * N_ * P_];
__device__ float g_Sprev[(size_t)B_ * NC_ * H_ * N_ * P_];
__device__ float g_y[(size_t)RB_ * DI_];
/* shared (head-independent) C.B dot matrix: [b*16+c][l:128][v:258 pad 264] */
__device__ float g_D[(size_t)B_ * NC_ * 128 * 264];

/* ------------------------------------------------------------------ */
/* bf16x3 tensor-core GEMM (R6 version: convert-in-smem).              */
/* ------------------------------------------------------------------ */
#define AST_STRIDE 36
#define BST_STRIDE 132
#define AST_SIZE (128*AST_STRIDE)
#define BST_SIZE (32*BST_STRIDE)
#define AP_STRIDE 20
#define BP_STRIDE 136
#define AP_SIZE  (128*AP_STRIDE)
#define BP_SIZE  (16*BP_STRIDE)
#define OFF_AST  0
#define OFF_BST  (2*AST_SIZE)
#define OFF_AH   (OFF_BST + 2*BST_SIZE)
#define OFF_AL   (OFF_AH + AP_SIZE)
#define OFF_BH   (OFF_AL + AP_SIZE)
#define OFF_BL   (OFF_BH + BP_SIZE)
#define GEMM_WORDS (OFF_BL + BP_SIZE)
#define GEMM_SMEM_BYTES (GEMM_WORDS * 4)

__device__ __forceinline__ uint32_t smem_u32(const void* p) {
    return (uint32_t)__cvta_generic_to_shared(p);
}
__device__ __forceinline__ void cp16(uint32_t dst, const void* src, int pred_bytes) {
    asm volatile("cp.async.cg.shared.global [%0], [%1], 16, %2;"
                 :: "r"(dst), "l"(src), "r"(pred_bytes));
}
__device__ __forceinline__ void f2bf2(float x0, float x1, uint32_t& h, uint32_t& l) {
    asm("cvt.rn.bf16x2.f32 %0, %1, %2;" : "=r"(h) : "f"(x1), "f"(x0));
    float h0 = __uint_as_float(h << 16);
    float h1 = __uint_as_float(h & 0xffff0000u);
    float l0 = x0 - h0, l1 = x1 - h1;
    asm("cvt.rn.bf16x2.f32 %0, %1, %2;" : "=r"(l) : "f"(l1), "f"(l0));
}
__device__ __forceinline__ void mma16(float* c, const uint32_t* a, const uint32_t* b) {
    asm volatile(
        "mma.sync.aligned.m16n8k16.row.col.f32.bf16.bf16.f32 "
        "{%0,%1,%2,%3}, {%4,%5,%6,%7}, {%8,%9}, {%0,%1,%2,%3};"
        : "+f"(c[0]), "+f"(c[1]), "+f"(c[2]), "+f"(c[3])
        : "r"(a[0]), "r"(a[1]), "r"(a[2]), "r"(a[3]), "r"(b[0]), "r"(b[1]));
}

__global__ __launch_bounds__(256, 2) void gemm_bf16x3(
    const float* __restrict__ A, const float* __restrict__ Bm,
    float* __restrict__ C, int M, int N, int K)
{
    extern __shared__ float sm[];
    float* ASt = sm + OFF_AST;
    float* BSt = sm + OFF_BST;
    uint32_t* Ah = (uint32_t*)(sm + OFF_AH);
    uint32_t* Al = (uint32_t*)(sm + OFF_AL);
    uint32_t* Bh = (uint32_t*)(sm + OFF_BH);
    uint32_t* Bl = (uint32_t*)(sm + OFF_BL);

    int tid = threadIdx.x;
    int bm = blockIdx.y * 128, bn = blockIdx.x * 128;
    int warp = tid >> 5, lane = tid & 31;
    int gid = lane >> 2, tig = lane & 3;
    int wm = (warp & 1) * 64;
    int wn = (warp >> 1) * 32;

    float acc[4][4][4];
#pragma unroll
    for (int mt = 0; mt < 4; mt++)
#pragma unroll
        for (int nt = 0; nt < 4; nt++)
#pragma unroll
            for (int q = 0; q < 4; q++) acc[mt][nt][q] = 0.f;

    int KTn = K >> 5;

#define PREFETCH(ktv, buf)                                                      \
    {                                                                           \
        int k0 = (ktv) << 5;                                                    \
        float* Ab_ = ASt + (buf) * AST_SIZE;                                    \
        float* Bb_ = BSt + (buf) * BST_SIZE;                                    \
        _Pragma("unroll")                                                       \
        for (int i = 0; i < 4; i++) {                                           \
            int idx = tid + i * 256;                                            \
            int row = idx >> 3, kc = (idx & 7) << 2;                            \
            cp16(smem_u32(&Ab_[row * AST_STRIDE + kc]),                         \
                 A + (size_t)(bm + row) * K + k0 + kc, 16);                     \
        }                                                                       \
        _Pragma("unroll")                                                       \
        for (int i = 0; i < 4; i++) {                                           \
            int idx = tid + i * 256;                                            \
            int row = idx >> 5, nc = (idx & 31) << 2;                           \
            int ok = (bn + nc) < N;                                             \
            const float* src = ok ? (Bm + (size_t)(k0 + row) * N + bn + nc) : Bm; \
            cp16(smem_u32(&Bb_[row * BST_STRIDE + nc]), src, ok ? 16 : 0);      \
        }                                                                       \
        asm volatile("cp.async.commit_group;");                                 \
    }

    PREFETCH(0, 0);

    for (int kt = 0; kt < KTn; kt++) {
        if (kt + 1 < KTn) {
            PREFETCH(kt + 1, (kt + 1) & 1);
            asm volatile("cp.async.wait_group 1;");
        } else {
            asm volatile("cp.async.wait_group 0;");
        }
        __syncthreads();

        {
            const float* Ab = ASt + (kt & 1) * AST_SIZE;
            const float* Bb = BSt + (kt & 1) * BST_SIZE;
            int mq = tid >> 4, kpA = tid & 15;
#pragma unroll
            for (int j = 0; j < 8; j++) {
                int m = j * 16 + mq;
                float2 v = *(const float2*)&Ab[m * AST_STRIDE + 2 * kpA];
                uint32_t hh, ll;
                f2bf2(v.x, v.y, hh, ll);
                Ah[m * AP_STRIDE + kpA] = hh;
                Al[m * AP_STRIDE + kpA] = ll;
            }
            int n = tid & 127, kq = tid >> 7;
#pragma unroll
            for (int j = 0; j < 8; j++) {
                int kp = j * 2 + kq;
                float b0 = Bb[(2 * kp) * BST_STRIDE + n];
                float b1 = Bb[(2 * kp + 1) * BST_STRIDE + n];
                uint32_t hh, ll;
                f2bf2(b0, b1, hh, ll);
                Bh[kp * BP_STRIDE + n] = hh;
                Bl[kp * BP_STRIDE + n] = ll;
            }
        }
        __syncthreads();

#pragma unroll
        for (int ks = 0; ks < 2; ks++) {
            int kp0 = ks * 8 + tig;
            uint32_t bh[4][2], bl[4][2];
#pragma unroll
            for (int nt = 0; nt < 4; nt++) {
                int n = wn + nt * 8 + gid;
                bh[nt][0] = Bh[kp0 * BP_STRIDE + n];
                bh[nt][1] = Bh[(kp0 + 4) * BP_STRIDE + n];
                bl[nt][0] = Bl[kp0 * BP_STRIDE + n];
                bl[nt][1] = Bl[(kp0 + 4) * BP_STRIDE + n];
            }
#pragma unroll
            for (int mt = 0; mt < 4; mt++) {
                int m0 = wm + mt * 16 + gid;
                uint32_t ah[4], al[4];
                ah[0] = Ah[m0 * AP_STRIDE + kp0];
                ah[1] = Ah[(m0 + 8) * AP_STRIDE + kp0];
                ah[2] = Ah[m0 * AP_STRIDE + kp0 + 4];
                ah[3] = Ah[(m0 + 8) * AP_STRIDE + kp0 + 4];
                al[0] = Al[m0 * AP_STRIDE + kp0];
                al[1] = Al[(m0 + 8) * AP_STRIDE + kp0];
                al[2] = Al[m0 * AP_STRIDE + kp0 + 4];
                al[3] = Al[(m0 + 8) * AP_STRIDE + kp0 + 4];
#pragma unroll
                for (int nt = 0; nt < 4; nt++) {
                    mma16(acc[mt][nt], ah, bh[nt]);
                    mma16(acc[mt][nt], al, bh[nt]);
                    mma16(acc[mt][nt], ah, bl[nt]);
                }
            }
        }
        __syncthreads();
    }

#pragma unroll
    for (int mt = 0; mt < 4; mt++) {
#pragma unroll
        for (int nt = 0; nt < 4; nt++) {
            int row0 = bm + wm + mt * 16 + gid;
            int col = bn + wn + nt * 8 + tig * 2;
            if (col < N) {
                *(float2*)&C[(size_t)row0 * N + col] =
                    make_float2(acc[mt][nt][0], acc[mt][nt][1]);
                *(float2*)&C[(size_t)(row0 + 8) * N + col] =
                    make_float2(acc[mt][nt][2], acc[mt][nt][3]);
            }
        }
    }
}

/* ------------------------------------------------------------------ */
/* 2. per-(b,t): dt/lambda/alpha + coefs, RMS of B/C, silu(x), mt      */
/* ------------------------------------------------------------------ */
__global__ __launch_bounds__(128) void act_kernel(
    const float* __restrict__ A_log, const float* __restrict__ dt_bias,
    const float* __restrict__ Bnb, const float* __restrict__ Cnb)
{
    int row = blockIdx.x;
    float* pr = g_proj + (size_t)row * DP_;
    int tid = threadIdx.x, lane = tid & 31, w = tid >> 5;
    __shared__ float red[8];

    if (w == 0) {
        int h = lane;
        float xr = pr[6336 + h] + dt_bias[h];
        float sp = (xr > 20.f) ? xr : log1pf(expf(xr));
        float dt = fminf(fmaxf(sp, 1e-4f), 0.5f);
        float A = -expf(A_log[h]);
        float ldA = dt * A;
        float lam = 1.f / (1.f + expf(-pr[6368 + h]));
        g_logdA[row * 32 + h] = ldA;
        g_acoef[row * 32 + h] = lam * dt;
        g_bcoef[row * 32 + h] = (1.f - lam) * dt * expf(ldA);
        float s = dt;
#pragma unroll
        for (int o = 16; o > 0; o >>= 1) s += __shfl_xor_sync(0xffffffffu, s, o);
        float md = s * (1.f / 32.f);
        g_mt[row * 32 + h] = md * pr[6400 + h];
    }

    float bv = pr[6144 + tid];
    float ss = bv * bv;
#pragma unroll
    for (int o = 16; o > 0; o >>= 1) ss += __shfl_xor_sync(0xffffffffu, ss, o);
    if (lane == 0) red[w] = ss;
    __syncthreads();
    {
        int r = tid >> 6, n = tid & 63;
        float sum = red[r * 2] + red[r * 2 + 1];
        g_Bn[(size_t)row * 128 + tid] = bv * rsqrtf(sum * (1.f / 64.f) + EPS_F) * Bnb[n];
    }

    float cv = 0.f, ss2 = 0.f;
    if (tid < 64) {
        cv = pr[6272 + tid];
        ss2 = cv * cv;
#pragma unroll
        for (int o = 16; o > 0; o >>= 1) ss2 += __shfl_xor_sync(0xffffffffu, ss2, o);
        if (lane == 0) red[4 + w] = ss2;
    }
    __syncthreads();
    if (tid < 64) {
        float sum = red[4] + red[5];
        g_Cn[(size_t)row * 64 + tid] = cv * rsqrtf(sum * (1.f / 64.f) + EPS_F) * Cnb[tid];
    }

    for (int j = tid; j < 4096; j += 128) {
        float v = pr[2048 + j];
        pr[2048 + j] = v / (1.f + expf(-v));
    }
}

/* ------------------------------------------------------------------ */
/* 3. full-T inclusive scan of mean_dt*theta -> cos/sin of -cumsum     */
/* ------------------------------------------------------------------ */
__global__ __launch_bounds__(256) void scan_ang_kernel()
{
    int bk = blockIdx.x;
    int b = bk >> 5, k = bk & 31;
    int tid = threadIdx.x;
    size_t base = ((size_t)b * T_) * 32 + k;
    float v[8];
    float run = 0.f;
#pragma unroll
    for (int j = 0; j < 8; j++) {
        run += g_mt[base + (size_t)(tid * 8 + j) * 32];
        v[j] = run;
    }
    __shared__ float s[256];
    s[tid] = run;
    __syncthreads();
    for (int off = 1; off < 256; off <<= 1) {
        float xv = (tid >= off) ? s[tid - off] : 0.f;
        __syncthreads();
        s[tid] += xv;
        __syncthreads();
    }
    float excl = s[tid] - run;
#pragma unroll
    for (int j = 0; j < 8; j++) {
        float ang = -(excl + v[j]);
        size_t idx = base + (size_t)(tid * 8 + j) * 32;
        g_cosb[idx] = cosf(ang);
        g_sinb[idx] = sinf(ang);
    }
}

/* ------------------------------------------------------------------ */
/* 4. RoPE for C and B(r=0,1)                                          */
/* ------------------------------------------------------------------ */
__global__ __launch_bounds__(32) void rope_kernel()
{
    int row = blockIdx.x;
    int k = threadIdx.x;
    float cs = g_cosb[(size_t)row * 32 + k], sn = g_sinb[(size_t)row * 32 + k];
    float c1 = g_Cn[(size_t)row * 64 + k], c2 = g_Cn[(size_t)row * 64 + 32 + k];
    g_Cr[(size_t)row * 64 + k] = c1 * cs - c2 * sn;
    g_Cr[(size_t)row * 64 + 32 + k] = c1 * sn + c2 * cs;
#pragma unroll
    for (int r = 0; r < 2; r++) {
        float b1 = g_Bn[(size_t)row * 128 + r * 64 + k];
        float b2 = g_Bn[(size_t)row * 128 + r * 64 + 32 + k];
        g_Br[(size_t)row * 128 + r * 64 + k] = b1 * cs - b2 * sn;
        g_Br[(size_t)row * 128 + r * 64 + 32 + k] = b1 * sn + b2 * cs;
    }
}

/* ------------------------------------------------------------------ */
/* 5. within-chunk inclusive cumsum of log dA (smem-staged)            */
/* ------------------------------------------------------------------ */
__global__ __launch_bounds__(128) void cum_kernel()
{
    __shared__ float s[128 * 32];
    int blk = blockIdx.x;
    int tid = threadIdx.x;
    size_t base = (size_t)blk * 128 * 32;
    for (int i = tid; i < 4096; i += 128) s[i] = g_logdA[base + i];
    __syncthreads();
    if (tid < 32) {
        float run = 0.f;
        for (int l = 0; l < 128; l++) {
            run += s[l * 32 + tid];
            s[l * 32 + tid] = run;
        }
    }
    __syncthreads();
    for (int i = tid; i < 4096; i += 128) g_cum[base + i] = s[i];
}

/* ------------------------------------------------------------------ */
/* 5b. s_kernel: per (b,c) shared dot matrix                           */
/* ------------------------------------------------------------------ */
#define SC_STRIDE 69
#define SBS_STRIDE 133
#define SMEM_S_FLOATS (128*SC_STRIDE + 129*SBS_STRIDE)
__global__ __launch_bounds__(256) void s_kernel()
{
    extern __shared__ float sm[];
    float* sC = sm;
    float* sB = sm + 128 * SC_STRIDE;
    int c = blockIdx.x, b = blockIdx.y;
    int tid = threadIdx.x;
    int t0 = c * L_;
    size_t rb = (size_t)b * T_ + t0;

    for (int i = tid; i < 128 * 64; i += 256) {
        int l = i >> 6, n = i & 63;
        sC[l * SC_STRIDE + n] = g_Cr[(rb + l) * 64 + n];
    }
    for (int i = tid; i < 129 * 128; i += 256) {
        int row = i >> 7, j = i & 127;
        int t = t0 + row - 1;
        sB[row * SBS_STRIDE + j] = (t >= 0) ? g_Br[((size_t)b * T_ + t) * 128 + j] : 0.f;
    }
    __syncthreads();

    int lt = tid >> 3;
    int vg = tid & 7;
    float* gD = g_D + (size_t)(b * 16 + c) * 128 * 264;

#pragma unroll
    for (int pass = 0; pass < 5; pass++) {
        int v0 = pass * 64 + vg * 8;
        if (v0 < 258) {
            int boff[8];
#pragma unroll
            for (int u = 0; u < 8; u++) {
                int v = v0 + u; if (v > 257) v = 257;
                boff[u] = (v >> 1) * SBS_STRIDE + (v & 1) * 64;
            }
            float acc[4][8];
#pragma unroll
            for (int q = 0; q < 4; q++)
#pragma unroll
                for (int u = 0; u < 8; u++) acc[q][u] = 0.f;
            const float* cp = sC + (lt * 4) * SC_STRIDE;
            for (int k = 0; k < 64; k++) {
                float cv[4];
#pragma unroll
                for (int q = 0; q < 4; q++) cv[q] = cp[q * SC_STRIDE + k];
                float bv[8];
#pragma unroll
                for (int u = 0; u < 8; u++) bv[u] = sB[boff[u] + k];
#pragma unroll
                for (int q = 0; q < 4; q++)
#pragma unroll
                    for (int u = 0; u < 8; u++) acc[q][u] += cv[q] * bv[u];
            }
#pragma unroll
            for (int q = 0; q < 4; q++) {
                float* drow = gD + (size_t)(lt * 4 + q) * 264 + v0;
#pragma unroll
                for (int u = 0; u < 8; u++)
                    if (v0 + u < 258) drow[u] = acc[q][u];
            }
        }
    }
}

/* ------------------------------------------------------------------ */
/* 6. fused per-(b,c,h) chunk kernel: y_intra + chunk state st         */
/* compile-time causal skip + pre-weighted dot tiles (sW)              */
/* ------------------------------------------------------------------ */
#define SMEM_CHUNK_FLOATS 42760
__global__ __launch_bounds__(256) void chunk_kernel()
{
    extern __shared__ float sm[];
    float* sB   = sm;             /* 17028 */
    float* sX   = sm + 17028;     /* 17028 */
    float* sW   = sm + 34056;     /* 8192: [l][mm][4] = dg*{d1x,d1y,d0x,d0y} */
    float* sCum = sm + 42248;     /* 128   */
    float* sA   = sm + 42376;     /* 128   */
    float* sBc  = sm + 42504;     /* 128   */
    float* sDE  = sm + 42632;     /* 128   */

    int h = blockIdx.x, c = blockIdx.y, b = blockIdx.z;
    int tid = threadIdx.x;
    int t0 = c * L_;
    size_t rb = (size_t)b * T_ + t0;
    const float* gD = g_D + (size_t)(b * 16 + c) * 128 * 264;

    for (int i = tid; i < 129 * 128; i += 256) {
        int row = i >> 7, j = i & 127;
        int t = t0 + row - 1;
        sB[row * 132 + j] = (t >= 0) ? g_Br[((size_t)b * T_ + t) * 128 + j] : 0.f;
    }
    for (int i = tid; i < 129 * 128; i += 256) {
        int row = i >> 7, j = i & 127;
        int t = t0 + row - 1;
        sX[row * 132 + j] = (t >= 0)
            ? g_proj[((size_t)b * T_ + t) * DP_ + 2048 + h * 128 + j] : 0.f;
    }
    if (tid < 128) {
        size_t g = (rb + tid) * 32 + h;
        sCum[tid] = g_cum[g];
        sA[tid] = g_acoef[g];
        sBc[tid] = g_bcoef[g];
    }
    __syncthreads();
    if (tid < 128) sDE[tid] = expf(sCum[127] - sCum[tid]);

    float acc[8][4];
#pragma unroll
    for (int i = 0; i < 8; i++)
#pragma unroll
        for (int q = 0; q < 4; q++) acc[i][q] = 0.f;

    int pg = tid & 15, p0 = pg << 2, lg = tid >> 4;

#pragma unroll
    for (int m0t = 0; m0t < 8; m0t++) {
        const int m0 = m0t << 4;
        /* stage A: pre-weighted dot tiles for rows l >= m0 */
        {
            int total = (128 - m0) * 16;
            for (int e = tid; e < total; e += 256) {
                int lr = e >> 4, mm = e & 15;
                int l = m0 + lr, m = m0 + mm;
                float dg = (m <= l) ? SCALE_F * expf(sCum[l] - sCum[m]) : 0.f;
                const float* gp = gD + (size_t)l * 264 + 2 * m0 + 2 * mm;
                float2 d0 = *(const float2*)gp;
                float2 d1 = *(const float2*)(gp + 2);
                *(float4*)&sW[(l << 6) + (mm << 2)] =
                    make_float4(d1.x * dg, d1.y * dg, d0.x * dg, d0.y * dg);
            }
        }
        __syncthreads();

        float4 xba = *(const float4*)&sX[m0 * 132 + p0];
        float4 xbb = *(const float4*)&sX[m0 * 132 + 64 + p0];

        for (int mm = 0; mm < 16; mm++) {
            int m = m0 + mm;
            float ea = sA[m], eb = sBc[m];
            float4 xga = *(const float4*)&sX[(m + 1) * 132 + p0];
            float4 xgb = *(const float4*)&sX[(m + 1) * 132 + 64 + p0];
            float xg0[4] = {ea * xga.x, ea * xga.y, ea * xga.z, ea * xga.w};
            float xg1[4] = {ea * xgb.x, ea * xgb.y, ea * xgb.z, ea * xgb.w};
            float xb0[4] = {eb * xba.x, eb * xba.y, eb * xba.z, eb * xba.w};
            float xb1[4] = {eb * xbb.x, eb * xbb.y, eb * xbb.z, eb * xbb.w};
#pragma unroll
            for (int jl = 0; jl < 8; jl++) {
                if (jl >= m0t) {          /* compile-time per unrolled m0t */
                    int l = lg + (jl << 4);
                    float4 w = *(const float4*)&sW[(l << 6) + (mm << 2)];
#pragma unroll
                    for (int q = 0; q < 4; q++) {
                        acc[jl][q] += w.x * xg0[q] + w.y * xg1[q]
                                    + w.z * xb0[q] + w.w * xb1[q];
                    }
                }
            }
            xba = xga; xbb = xgb;
        }
        __syncthreads();
    }
#pragma unroll
    for (int jl = 0; jl < 8; jl++) {
        int l = lg + (jl << 4);
        float4 outv = make_float4(acc[jl][0], acc[jl][1], acc[jl][2], acc[jl][3]);
        *(float4*)&g_y[(rb + l) * (size_t)DI_ + h * 64 + p0] = outv;
    }

    /* chunk state st[n][p]: vectorized broadcast loads + row carry */
    int p = tid & 63, ng = tid >> 6;
    int n0 = ng << 4;
    float st[16];
#pragma unroll
    for (int jn = 0; jn < 16; jn++) st[jn] = 0.f;
    float cg[16], chh[16];
#pragma unroll
    for (int j = 0; j < 4; j++) {
        *(float4*)&cg[4 * j]  = *(const float4*)&sB[n0 + 4 * j];
        *(float4*)&chh[4 * j] = *(const float4*)&sB[64 + n0 + 4 * j];
    }
    float xprev0 = sX[p], xprev1 = sX[64 + p];
    for (int m = 0; m < 128; m++) {
        float e = sDE[m];
        float eg = e * sA[m], ebk = e * sBc[m];
        float xnext0 = sX[(m + 1) * 132 + p];
        float xnext1 = sX[(m + 1) * 132 + 64 + p];
        float xg0 = eg * xnext0;
        float xg1 = eg * xnext1;
        float xb0 = ebk * xprev0;
        float xb1 = ebk * xprev1;
        float ngv[16], nhv[16];
#pragma unroll
        for (int j = 0; j < 4; j++) {
            *(float4*)&ngv[4 * j] = *(const float4*)&sB[(m + 1) * 132 + n0 + 4 * j];
            *(float4*)&nhv[4 * j] = *(const float4*)&sB[(m + 1) * 132 + 64 + n0 + 4 * j];
        }
#pragma unroll
        for (int jn = 0; jn < 16; jn++) {
            st[jn] += ngv[jn] * xg0 + nhv[jn] * xg1 + cg[jn] * xb0 + chh[jn] * xb1;
        }
#pragma unroll
        for (int jn = 0; jn < 16; jn++) { cg[jn] = ngv[jn]; chh[jn] = nhv[jn]; }
        xprev0 = xnext0; xprev1 = xnext1;
    }
    size_t so = (((size_t)(b * 16 + c) * 32 + h) * 4096);
#pragma unroll
    for (int jn = 0; jn < 16; jn++)
        g_st[so + (size_t)(n0 + jn) * 64 + p] = st[jn];
}

/* ------------------------------------------------------------------ */
/* 7. inter-chunk state scan (16 steps)                                */
/* ------------------------------------------------------------------ */
__global__ __launch_bounds__(256) void scan_chunks_kernel()
{
    int b = blockIdx.x >> 5, h = blockIdx.x & 31;
    int tid = threadIdx.x;
    float S[16];
#pragma unroll
    for (int j = 0; j < 16; j++) S[j] = 0.f;
    for (int c = 0; c < 16; c++) {
        float cdec = expf(g_cum[((size_t)(b * 2048 + c * 128 + 127)) * 32 + h]);
        size_t off0 = (((size_t)(b * 16 + c) * 32 + h) * 4096);
#pragma unroll
        for (int j = 0; j < 16; j++) {
            size_t off = off0 + tid + j * 256;
            g_Sprev[off] = S[j];
            S[j] = cdec * S[j] + g_st[off];
        }
    }
}

/* ------------------------------------------------------------------ */
/* 8. y += SCALE * dec_in * (C @ Sprev)                                */
/* ------------------------------------------------------------------ */
#define SMEM_INTER_FLOATS (64*68 + 128*68 + 128)
__global__ __launch_bounds__(256) void inter_kernel()
{
    extern __shared__ float sm[];
    float* sS = sm;
    float* sC = sm + 64 * 68;
    float* sDec = sC + 128 * 68;
    int h = blockIdx.x, c = blockIdx.y, b = blockIdx.z;
    int tid = threadIdx.x;
    int t0 = c * 128;
    size_t rb = (size_t)b * T_ + t0;
    size_t soff = (((size_t)(b * 16 + c) * 32 + h) * 4096);

    for (int i = tid; i < 4096; i += 256)
        sS[(i >> 6) * 68 + (i & 63)] = g_Sprev[soff + i];
    for (int i = tid; i < 128 * 64; i += 256) {
        int l = i >> 6, n = i & 63;
        sC[l * 68 + n] = g_Cr[(rb + l) * 64 + n];
    }
    if (tid < 128) sDec[tid] = expf(g_cum[(rb + tid) * 32 + h]);
    __syncthreads();

    int pg = tid & 15, p0 = pg << 2, lg = tid >> 4;
#pragma unroll
    for (int jl = 0; jl < 8; jl++) {
        int l = lg + (jl << 4);
        float a0 = 0.f, a1 = 0.f, a2 = 0.f, a3 = 0.f;
#pragma unroll
        for (int n = 0; n < 64; n++) {
            float cv = sC[l * 68 + n];
            const float* sp = &sS[n * 68 + p0];
            a0 += cv * sp[0]; a1 += cv * sp[1];
            a2 += cv * sp[2]; a3 += cv * sp[3];
        }
        float coef = SCALE_F * sDec[l];
        float* yp = &g_y[(rb + l) * (size_t)DI_ + h * 64 + p0];
        yp[0] += coef * a0; yp[1] += coef * a1;
        yp[2] += coef * a2; yp[3] += coef * a3;
    }
}

/* ------------------------------------------------------------------ */
/* 9. y = rms(y * silu(z))                                             */
/* ------------------------------------------------------------------ */
__global__ __launch_bounds__(256) void gate_kernel()
{
    int row = blockIdx.x;
    int tid = threadIdx.x, lane = tid & 31, w = tid >> 5;
    const float* z = g_proj + (size_t)row * DP_;
    float* y = g_y + (size_t)row * DI_;
    float v[8];
    float ss = 0.f;
#pragma unroll
    for (int j = 0; j < 8; j++) {
        int i = tid + j * 256;
        float zv = z[i];
        float sz = zv / (1.f + expf(-zv));
        float vv = y[i] * sz;
        v[j] = vv;
        ss += vv * vv;
    }
#pragma unroll
    for (int o = 16; o > 0; o >>= 1) ss += __shfl_xor_sync(0xffffffffu, ss, o);
    __shared__ float red[8];
    if (lane == 0) red[w] = ss;
    __syncthreads();
    float tot = red[0] + red[1] + red[2] + red[3] + red[4] + red[5] + red[6] + red[7];
    float rinv = rsqrtf(tot * (1.f / 2048.f) + EPS_F);
#pragma unroll
    for (int j = 0; j < 8; j++) y[tid + j * 256] = v[j] * rinv;
}

/* ------------------------------------------------------------------ */
extern "C" void kernel_launch(void* const* d_in, const int* in_sizes, int n_in,
                              void* d_out, int out_size)
{
    const float* x       = (const float*)d_in[0];
    const float* W_in    = (const float*)d_in[1];
    const float* A_log   = (const float*)d_in[2];
    const float* dt_bias = (const float*)d_in[3];
    const float* Bnb     = (const float*)d_in[4];
    const float* Cnb     = (const float*)d_in[5];
    const float* W_out   = (const float*)d_in[6];
    float* out = (float*)d_out;

    void *p_proj = 0, *p_y = 0;
    cudaGetSymbolAddress(&p_proj, g_proj);
    cudaGetSymbolAddress(&p_y, g_y);

    cudaFuncSetAttribute(gemm_bf16x3, cudaFuncAttributeMaxDynamicSharedMemorySize,
                         GEMM_SMEM_BYTES);
    cudaFuncSetAttribute(s_kernel, cudaFuncAttributeMaxDynamicSharedMemorySize,
                         SMEM_S_FLOATS * 4);
    cudaFuncSetAttribute(chunk_kernel, cudaFuncAttributeMaxDynamicSharedMemorySize,
                         SMEM_CHUNK_FLOATS * 4);
    cudaFuncSetAttribute(inter_kernel, cudaFuncAttributeMaxDynamicSharedMemorySize,
                         SMEM_INTER_FLOATS * 4);

    /* 1. in-proj */
    gemm_bf16x3<<<dim3((DP_ + 127) / 128, RB_ / 128), 256, GEMM_SMEM_BYTES>>>(
        x, W_in, (float*)p_proj, RB_, DP_, DM_);
    /* 2. activations */
    act_kernel<<<RB_, 128>>>(A_log, dt_bias, Bnb, Cnb);
    /* 3. angle scan */
    scan_ang_kernel<<<B_ * 32, 256>>>();
    /* 4. rope */
    rope_kernel<<<RB_, 32>>>();
    /* 5. chunk cumsum */
    cum_kernel<<<B_ * NC_, 128>>>();
    /* 5b. shared dot matrix */
    s_kernel<<<dim3(NC_, B_), 256, SMEM_S_FLOATS * 4>>>();
    /* 6. fused chunk */
    chunk_kernel<<<dim3(H_, NC_, B_), 256, SMEM_CHUNK_FLOATS * 4>>>();
    /* 7. state scan */
    scan_chunks_kernel<<<B_ * H_, 256>>>();
    /* 8. inter */
    inter_kernel<<<dim3(H_, NC_, B_), 256, SMEM_INTER_FLOATS * 4>>>();
    /* 9. gate + rms */
    gate_kernel<<<RB_, 256>>>();
    /* 10. out-proj */
    gemm_bf16x3<<<dim3(DM_ / 128, RB_ / 128), 256, GEMM_SMEM_BYTES>>>(
        (const float*)p_y, W_out, out, RB_, DM_, DI_);
}

// round 15
// speedup vs baseline: 1.2270x; 1.0668x over previous
#include <cuda_runtime.h>
#include <math.h>
#include <stdint.h>

#define B_   2
#define T_   2048
#define DM_  1024
#define DP_  6432
#define DI_  2048
#define H_   32
#define P_   64
#define N_   64
#define L_   128
#define NC_  16
#define RB_  (B_*T_)          /* 4096 rows */
#define SCALE_F 0.08838834764831845f  /* 1/sqrt(128) */
#define EPS_F 1e-6f

/* ------------------------------------------------------------------ */
/* scratch (static device globals: allocation-free, graph-safe)        */
/* ------------------------------------------------------------------ */
__device__ float g_proj[(size_t)RB_ * DP_];       /* 105 MB */
__device__ float g_logdA[RB_ * H_];
__device__ float g_acoef[RB_ * H_];
__device__ float g_bcoef[RB_ * H_];
__device__ float g_mt[RB_ * H_];
__device__ float g_cosb[RB_ * H_];
__device__ float g_sinb[RB_ * H_];
__device__ float g_cum[RB_ * H_];
__device__ float g_Bn[RB_ * 128];
__device__ float g_Cn[RB_ * 64];
__device__ float g_Br[RB_ * 128];
__device__ float g_Cr[RB_ * 64];
__device__ float g_st[(size_t)B_ * NC_ * H_ * N_ * P_];
__device__ float g_Sprev[(size_t)B_ * NC_ * H_ * N_ * P_];
__device__ float g_y[(size_t)RB_ * DI_];
/* shared (head-independent) C.B dot matrix: [b*16+c][l:128][v:258 pad 264] */
__device__ float g_D[(size_t)B_ * NC_ * 128 * 264];

/* ------------------------------------------------------------------ */
/* bf16x3 tensor-core GEMM (R6 version: convert-in-smem).              */
/* ------------------------------------------------------------------ */
#define AST_STRIDE 36
#define BST_STRIDE 132
#define AST_SIZE (128*AST_STRIDE)
#define BST_SIZE (32*BST_STRIDE)
#define AP_STRIDE 20
#define BP_STRIDE 136
#define AP_SIZE  (128*AP_STRIDE)
#define BP_SIZE  (16*BP_STRIDE)
#define OFF_AST  0
#define OFF_BST  (2*AST_SIZE)
#define OFF_AH   (OFF_BST + 2*BST_SIZE)
#define OFF_AL   (OFF_AH + AP_SIZE)
#define OFF_BH   (OFF_AL + AP_SIZE)
#define OFF_BL   (OFF_BH + BP_SIZE)
#define GEMM_WORDS (OFF_BL + BP_SIZE)
#define GEMM_SMEM_BYTES (GEMM_WORDS * 4)

__device__ __forceinline__ uint32_t smem_u32(const void* p) {
    return (uint32_t)__cvta_generic_to_shared(p);
}
__device__ __forceinline__ void cp16(uint32_t dst, const void* src, int pred_bytes) {
    asm volatile("cp.async.cg.shared.global [%0], [%1], 16, %2;"
                 :: "r"(dst), "l"(src), "r"(pred_bytes));
}
__device__ __forceinline__ void f2bf2(float x0, float x1, uint32_t& h, uint32_t& l) {
    asm("cvt.rn.bf16x2.f32 %0, %1, %2;" : "=r"(h) : "f"(x1), "f"(x0));
    float h0 = __uint_as_float(h << 16);
    float h1 = __uint_as_float(h & 0xffff0000u);
    float l0 = x0 - h0, l1 = x1 - h1;
    asm("cvt.rn.bf16x2.f32 %0, %1, %2;" : "=r"(l) : "f"(l1), "f"(l0));
}
__device__ __forceinline__ void mma16(float* c, const uint32_t* a, const uint32_t* b) {
    asm volatile(
        "mma.sync.aligned.m16n8k16.row.col.f32.bf16.bf16.f32 "
        "{%0,%1,%2,%3}, {%4,%5,%6,%7}, {%8,%9}, {%0,%1,%2,%3};"
        : "+f"(c[0]), "+f"(c[1]), "+f"(c[2]), "+f"(c[3])
        : "r"(a[0]), "r"(a[1]), "r"(a[2]), "r"(a[3]), "r"(b[0]), "r"(b[1]));
}

__global__ __launch_bounds__(256, 2) void gemm_bf16x3(
    const float* __restrict__ A, const float* __restrict__ Bm,
    float* __restrict__ C, int M, int N, int K)
{
    extern __shared__ float sm[];
    float* ASt = sm + OFF_AST;
    float* BSt = sm + OFF_BST;
    uint32_t* Ah = (uint32_t*)(sm + OFF_AH);
    uint32_t* Al = (uint32_t*)(sm + OFF_AL);
    uint32_t* Bh = (uint32_t*)(sm + OFF_BH);
    uint32_t* Bl = (uint32_t*)(sm + OFF_BL);

    int tid = threadIdx.x;
    int bm = blockIdx.y * 128, bn = blockIdx.x * 128;
    int warp = tid >> 5, lane = tid & 31;
    int gid = lane >> 2, tig = lane & 3;
    int wm = (warp & 1) * 64;
    int wn = (warp >> 1) * 32;

    float acc[4][4][4];
#pragma unroll
    for (int mt = 0; mt < 4; mt++)
#pragma unroll
        for (int nt = 0; nt < 4; nt++)
#pragma unroll
            for (int q = 0; q < 4; q++) acc[mt][nt][q] = 0.f;

    int KTn = K >> 5;

#define PREFETCH(ktv, buf)                                                      \
    {                                                                           \
        int k0 = (ktv) << 5;                                                    \
        float* Ab_ = ASt + (buf) * AST_SIZE;                                    \
        float* Bb_ = BSt + (buf) * BST_SIZE;                                    \
        _Pragma("unroll")                                                       \
        for (int i = 0; i < 4; i++) {                                           \
            int idx = tid + i * 256;                                            \
            int row = idx >> 3, kc = (idx & 7) << 2;                            \
            cp16(smem_u32(&Ab_[row * AST_STRIDE + kc]),                         \
                 A + (size_t)(bm + row) * K + k0 + kc, 16);                     \
        }                                                                       \
        _Pragma("unroll")                                                       \
        for (int i = 0; i < 4; i++) {                                           \
            int idx = tid + i * 256;                                            \
            int row = idx >> 5, nc = (idx & 31) << 2;                           \
            int ok = (bn + nc) < N;                                             \
            const float* src = ok ? (Bm + (size_t)(k0 + row) * N + bn + nc) : Bm; \
            cp16(smem_u32(&Bb_[row * BST_STRIDE + nc]), src, ok ? 16 : 0);      \
        }                                                                       \
        asm volatile("cp.async.commit_group;");                                 \
    }

    PREFETCH(0, 0);

    for (int kt = 0; kt < KTn; kt++) {
        if (kt + 1 < KTn) {
            PREFETCH(kt + 1, (kt + 1) & 1);
            asm volatile("cp.async.wait_group 1;");
        } else {
            asm volatile("cp.async.wait_group 0;");
        }
        __syncthreads();

        {
            const float* Ab = ASt + (kt & 1) * AST_SIZE;
            const float* Bb = BSt + (kt & 1) * BST_SIZE;
            int mq = tid >> 4, kpA = tid & 15;
#pragma unroll
            for (int j = 0; j < 8; j++) {
                int m = j * 16 + mq;
                float2 v = *(const float2*)&Ab[m * AST_STRIDE + 2 * kpA];
                uint32_t hh, ll;
                f2bf2(v.x, v.y, hh, ll);
                Ah[m * AP_STRIDE + kpA] = hh;
                Al[m * AP_STRIDE + kpA] = ll;
            }
            int n = tid & 127, kq = tid >> 7;
#pragma unroll
            for (int j = 0; j < 8; j++) {
                int kp = j * 2 + kq;
                float b0 = Bb[(2 * kp) * BST_STRIDE + n];
                float b1 = Bb[(2 * kp + 1) * BST_STRIDE + n];
                uint32_t hh, ll;
                f2bf2(b0, b1, hh, ll);
                Bh[kp * BP_STRIDE + n] = hh;
                Bl[kp * BP_STRIDE + n] = ll;
            }
        }
        __syncthreads();

#pragma unroll
        for (int ks = 0; ks < 2; ks++) {
            int kp0 = ks * 8 + tig;
            uint32_t bh[4][2], bl[4][2];
#pragma unroll
            for (int nt = 0; nt < 4; nt++) {
                int n = wn + nt * 8 + gid;
                bh[nt][0] = Bh[kp0 * BP_STRIDE + n];
                bh[nt][1] = Bh[(kp0 + 4) * BP_STRIDE + n];
                bl[nt][0] = Bl[kp0 * BP_STRIDE + n];
                bl[nt][1] = Bl[(kp0 + 4) * BP_STRIDE + n];
            }
#pragma unroll
            for (int mt = 0; mt < 4; mt++) {
                int m0 = wm + mt * 16 + gid;
                uint32_t ah[4], al[4];
                ah[0] = Ah[m0 * AP_STRIDE + kp0];
                ah[1] = Ah[(m0 + 8) * AP_STRIDE + kp0];
                ah[2] = Ah[m0 * AP_STRIDE + kp0 + 4];
                ah[3] = Ah[(m0 + 8) * AP_STRIDE + kp0 + 4];
                al[0] = Al[m0 * AP_STRIDE + kp0];
                al[1] = Al[(m0 + 8) * AP_STRIDE + kp0];
                al[2] = Al[m0 * AP_STRIDE + kp0 + 4];
                al[3] = Al[(m0 + 8) * AP_STRIDE + kp0 + 4];
#pragma unroll
                for (int nt = 0; nt < 4; nt++) {
                    mma16(acc[mt][nt], ah, bh[nt]);
                    mma16(acc[mt][nt], al, bh[nt]);
                    mma16(acc[mt][nt], ah, bl[nt]);
                }
            }
        }
        __syncthreads();
    }

#pragma unroll
    for (int mt = 0; mt < 4; mt++) {
#pragma unroll
        for (int nt = 0; nt < 4; nt++) {
            int row0 = bm + wm + mt * 16 + gid;
            int col = bn + wn + nt * 8 + tig * 2;
            if (col < N) {
                *(float2*)&C[(size_t)row0 * N + col] =
                    make_float2(acc[mt][nt][0], acc[mt][nt][1]);
                *(float2*)&C[(size_t)(row0 + 8) * N + col] =
                    make_float2(acc[mt][nt][2], acc[mt][nt][3]);
            }
        }
    }
}

/* ------------------------------------------------------------------ */
/* 2. per-(b,t): dt/lambda/alpha + coefs, RMS of B/C, silu(x), mt      */
/* ------------------------------------------------------------------ */
__global__ __launch_bounds__(128) void act_kernel(
    const float* __restrict__ A_log, const float* __restrict__ dt_bias,
    const float* __restrict__ Bnb, const float* __restrict__ Cnb)
{
    int row = blockIdx.x;
    float* pr = g_proj + (size_t)row * DP_;
    int tid = threadIdx.x, lane = tid & 31, w = tid >> 5;
    __shared__ float red[8];

    if (w == 0) {
        int h = lane;
        float xr = pr[6336 + h] + dt_bias[h];
        float sp = (xr > 20.f) ? xr : log1pf(expf(xr));
        float dt = fminf(fmaxf(sp, 1e-4f), 0.5f);
        float A = -expf(A_log[h]);
        float ldA = dt * A;
        float lam = 1.f / (1.f + expf(-pr[6368 + h]));
        g_logdA[row * 32 + h] = ldA;
        g_acoef[row * 32 + h] = lam * dt;
        g_bcoef[row * 32 + h] = (1.f - lam) * dt * expf(ldA);
        float s = dt;
#pragma unroll
        for (int o = 16; o > 0; o >>= 1) s += __shfl_xor_sync(0xffffffffu, s, o);
        float md = s * (1.f / 32.f);
        g_mt[row * 32 + h] = md * pr[6400 + h];
    }

    float bv = pr[6144 + tid];
    float ss = bv * bv;
#pragma unroll
    for (int o = 16; o > 0; o >>= 1) ss += __shfl_xor_sync(0xffffffffu, ss, o);
    if (lane == 0) red[w] = ss;
    __syncthreads();
    {
        int r = tid >> 6, n = tid & 63;
        float sum = red[r * 2] + red[r * 2 + 1];
        g_Bn[(size_t)row * 128 + tid] = bv * rsqrtf(sum * (1.f / 64.f) + EPS_F) * Bnb[n];
    }

    float cv = 0.f, ss2 = 0.f;
    if (tid < 64) {
        cv = pr[6272 + tid];
        ss2 = cv * cv;
#pragma unroll
        for (int o = 16; o > 0; o >>= 1) ss2 += __shfl_xor_sync(0xffffffffu, ss2, o);
        if (lane == 0) red[4 + w] = ss2;
    }
    __syncthreads();
    if (tid < 64) {
        float sum = red[4] + red[5];
        g_Cn[(size_t)row * 64 + tid] = cv * rsqrtf(sum * (1.f / 64.f) + EPS_F) * Cnb[tid];
    }

    for (int j = tid; j < 4096; j += 128) {
        float v = pr[2048 + j];
        pr[2048 + j] = v / (1.f + expf(-v));
    }
}

/* ------------------------------------------------------------------ */
/* 3. full-T inclusive scan of mean_dt*theta -> cos/sin of -cumsum     */
/* ------------------------------------------------------------------ */
__global__ __launch_bounds__(256) void scan_ang_kernel()
{
    int bk = blockIdx.x;
    int b = bk >> 5, k = bk & 31;
    int tid = threadIdx.x;
    size_t base = ((size_t)b * T_) * 32 + k;
    float v[8];
    float run = 0.f;
#pragma unroll
    for (int j = 0; j < 8; j++) {
        run += g_mt[base + (size_t)(tid * 8 + j) * 32];
        v[j] = run;
    }
    __shared__ float s[256];
    s[tid] = run;
    __syncthreads();
    for (int off = 1; off < 256; off <<= 1) {
        float xv = (tid >= off) ? s[tid - off] : 0.f;
        __syncthreads();
        s[tid] += xv;
        __syncthreads();
    }
    float excl = s[tid] - run;
#pragma unroll
    for (int j = 0; j < 8; j++) {
        float ang = -(excl + v[j]);
        size_t idx = base + (size_t)(tid * 8 + j) * 32;
        g_cosb[idx] = cosf(ang);
        g_sinb[idx] = sinf(ang);
    }
}

/* ------------------------------------------------------------------ */
/* 4. RoPE for C and B(r=0,1)                                          */
/* ------------------------------------------------------------------ */
__global__ __launch_bounds__(32) void rope_kernel()
{
    int row = blockIdx.x;
    int k = threadIdx.x;
    float cs = g_cosb[(size_t)row * 32 + k], sn = g_sinb[(size_t)row * 32 + k];
    float c1 = g_Cn[(size_t)row * 64 + k], c2 = g_Cn[(size_t)row * 64 + 32 + k];
    g_Cr[(size_t)row * 64 + k] = c1 * cs - c2 * sn;
    g_Cr[(size_t)row * 64 + 32 + k] = c1 * sn + c2 * cs;
#pragma unroll
    for (int r = 0; r < 2; r++) {
        float b1 = g_Bn[(size_t)row * 128 + r * 64 + k];
        float b2 = g_Bn[(size_t)row * 128 + r * 64 + 32 + k];
        g_Br[(size_t)row * 128 + r * 64 + k] = b1 * cs - b2 * sn;
        g_Br[(size_t)row * 128 + r * 64 + 32 + k] = b1 * sn + b2 * cs;
    }
}

/* ------------------------------------------------------------------ */
/* 5. within-chunk inclusive cumsum of log dA (smem-staged)            */
/* ------------------------------------------------------------------ */
__global__ __launch_bounds__(128) void cum_kernel()
{
    __shared__ float s[128 * 32];
    int blk = blockIdx.x;
    int tid = threadIdx.x;
    size_t base = (size_t)blk * 128 * 32;
    for (int i = tid; i < 4096; i += 128) s[i] = g_logdA[base + i];
    __syncthreads();
    if (tid < 32) {
        float run = 0.f;
        for (int l = 0; l < 128; l++) {
            run += s[l * 32 + tid];
            s[l * 32 + tid] = run;
        }
    }
    __syncthreads();
    for (int i = tid; i < 4096; i += 128) g_cum[base + i] = s[i];
}

/* ------------------------------------------------------------------ */
/* 5b. s_kernel: per (b,c) shared dot matrix                           */
/* ------------------------------------------------------------------ */
#define SC_STRIDE 69
#define SBS_STRIDE 133
#define SMEM_S_FLOATS (128*SC_STRIDE + 129*SBS_STRIDE)
__global__ __launch_bounds__(256) void s_kernel()
{
    extern __shared__ float sm[];
    float* sC = sm;
    float* sB = sm + 128 * SC_STRIDE;
    int c = blockIdx.x, b = blockIdx.y;
    int tid = threadIdx.x;
    int t0 = c * L_;
    size_t rb = (size_t)b * T_ + t0;

    for (int i = tid; i < 128 * 64; i += 256) {
        int l = i >> 6, n = i & 63;
        sC[l * SC_STRIDE + n] = g_Cr[(rb + l) * 64 + n];
    }
    for (int i = tid; i < 129 * 128; i += 256) {
        int row = i >> 7, j = i & 127;
        int t = t0 + row - 1;
        sB[row * SBS_STRIDE + j] = (t >= 0) ? g_Br[((size_t)b * T_ + t) * 128 + j] : 0.f;
    }
    __syncthreads();

    int lt = tid >> 3;
    int vg = tid & 7;
    float* gD = g_D + (size_t)(b * 16 + c) * 128 * 264;

#pragma unroll
    for (int pass = 0; pass < 5; pass++) {
        int v0 = pass * 64 + vg * 8;
        if (v0 < 258) {
            int boff[8];
#pragma unroll
            for (int u = 0; u < 8; u++) {
                int v = v0 + u; if (v > 257) v = 257;
                boff[u] = (v >> 1) * SBS_STRIDE + (v & 1) * 64;
            }
            float acc[4][8];
#pragma unroll
            for (int q = 0; q < 4; q++)
#pragma unroll
                for (int u = 0; u < 8; u++) acc[q][u] = 0.f;
            const float* cp = sC + (lt * 4) * SC_STRIDE;
            for (int k = 0; k < 64; k++) {
                float cv[4];
#pragma unroll
                for (int q = 0; q < 4; q++) cv[q] = cp[q * SC_STRIDE + k];
                float bv[8];
#pragma unroll
                for (int u = 0; u < 8; u++) bv[u] = sB[boff[u] + k];
#pragma unroll
                for (int q = 0; q < 4; q++)
#pragma unroll
                    for (int u = 0; u < 8; u++) acc[q][u] += cv[q] * bv[u];
            }
#pragma unroll
            for (int q = 0; q < 4; q++) {
                float* drow = gD + (size_t)(lt * 4 + q) * 264 + v0;
#pragma unroll
                for (int u = 0; u < 8; u++)
                    if (v0 + u < 258) drow[u] = acc[q][u];
            }
        }
    }
}

/* ------------------------------------------------------------------ */
/* 6. fused per-(b,c,h) chunk kernel: y_intra + chunk state st         */
/* telescoped g/b terms: 2-weight inner product, causal tile skip      */
/* ------------------------------------------------------------------ */
#define SMEM_CHUNK_FLOATS 38984
__global__ __launch_bounds__(256) void chunk_kernel()
{
    extern __shared__ float sm[];
    float* sB   = sm;             /* 17028 */
    float* sX   = sm + 17028;     /* 17028 */
    float* sW   = sm + 34056;     /* 4352: [l][jj] float2 (17 cols max) */
    float* sFa  = sm + 38408;     /* 32 */
    float* sFb  = sm + 38440;     /* 32 */
    float* sCum = sm + 38472;     /* 128 */
    float* sA   = sm + 38600;     /* 128 */
    float* sBc  = sm + 38728;     /* 128 */
    float* sDE  = sm + 38856;     /* 128 */

    int h = blockIdx.x, c = blockIdx.y, b = blockIdx.z;
    int tid = threadIdx.x;
    int t0 = c * L_;
    size_t rb = (size_t)b * T_ + t0;
    const float* gD = g_D + (size_t)(b * 16 + c) * 128 * 264;

    for (int i = tid; i < 129 * 128; i += 256) {
        int row = i >> 7, j = i & 127;
        int t = t0 + row - 1;
        sB[row * 132 + j] = (t >= 0) ? g_Br[((size_t)b * T_ + t) * 128 + j] : 0.f;
    }
    for (int i = tid; i < 129 * 128; i += 256) {
        int row = i >> 7, j = i & 127;
        int t = t0 + row - 1;
        sX[row * 132 + j] = (t >= 0)
            ? g_proj[((size_t)b * T_ + t) * DP_ + 2048 + h * 128 + j] : 0.f;
    }
    if (tid < 128) {
        size_t g = (rb + tid) * 32 + h;
        sCum[tid] = g_cum[g];
        sA[tid] = g_acoef[g];
        sBc[tid] = g_bcoef[g];
    }
    __syncthreads();
    if (tid < 128) sDE[tid] = expf(sCum[127] - sCum[tid]);

    float acc[8][4];
#pragma unroll
    for (int i = 0; i < 8; i++)
#pragma unroll
        for (int q = 0; q < 4; q++) acc[i][q] = 0.f;

    int pg = tid & 15, p0 = pg << 2, lg = tid >> 4;

#pragma unroll
    for (int jt = 0; jt < 8; jt++) {
        const int jbase = (jt == 0) ? 0 : (16 * jt + 1);
        const int ncol  = (jt == 0) ? 17 : 16;
        const int l0 = 16 * jt;
        float base = sCum[l0];
        /* per-column weights fa (g-term, from j-1) and fb (b-term, at j) */
        if (tid < ncol) {
            int j = jbase + tid;
            sFa[tid] = (j >= 1)   ? SCALE_F * expf(base - sCum[j - 1]) * sA[j - 1] : 0.f;
            sFb[tid] = (j <= 127) ? SCALE_F * expf(base - sCum[j]) * sBc[j] : 0.f;
        }
        __syncthreads();
        /* stage A: pre-weighted dot columns, rows l >= l0 */
        {
            int total = (128 - l0) * ncol;
            for (int e = tid; e < total; e += 256) {
                int lr = e / ncol, jj = e - lr * ncol;
                int l = l0 + lr, j = jbase + jj;
                float el = expf(sCum[l] - base);
                float wc = el * (((l >= j - 1) ? sFa[jj] : 0.f)
                               + ((l >= j) ? sFb[jj] : 0.f));
                float2 d = *(const float2*)(gD + (size_t)l * 264 + 2 * j);
                *(float2*)&sW[(l * 17 + jj) * 2] = make_float2(d.x * wc, d.y * wc);
            }
        }
        __syncthreads();
        /* stage B: 2-weight inner product */
        for (int jj = 0; jj < ncol; jj++) {
            int j = jbase + jj;
            float4 X0 = *(const float4*)&sX[j * 132 + p0];
            float4 X1 = *(const float4*)&sX[j * 132 + 64 + p0];
#pragma unroll
            for (int jl = 0; jl < 8; jl++) {
                if (jl >= jt) {      /* compile-time per unrolled jt */
                    int l = lg + (jl << 4);
                    float2 w = *(const float2*)&sW[(l * 17 + jj) * 2];
                    acc[jl][0] += w.x * X0.x + w.y * X1.x;
                    acc[jl][1] += w.x * X0.y + w.y * X1.y;
                    acc[jl][2] += w.x * X0.z + w.y * X1.z;
                    acc[jl][3] += w.x * X0.w + w.y * X1.w;
                }
            }
        }
        __syncthreads();
    }
#pragma unroll
    for (int jl = 0; jl < 8; jl++) {
        int l = lg + (jl << 4);
        float4 outv = make_float4(acc[jl][0], acc[jl][1], acc[jl][2], acc[jl][3]);
        *(float4*)&g_y[(rb + l) * (size_t)DI_ + h * 64 + p0] = outv;
    }

    /* chunk state st[n][p]: telescoped single-row form */
    int p = tid & 63, ng = tid >> 6;
    int n0 = ng << 4;
    float st[16];
#pragma unroll
    for (int jn = 0; jn < 16; jn++) st[jn] = 0.f;
    for (int j = 0; j <= 128; j++) {
        float w = 0.f;
        if (j >= 1)   w += sDE[j - 1] * sA[j - 1];
        if (j <= 127) w += sDE[j] * sBc[j];
        float wx0 = w * sX[j * 132 + p];
        float wx1 = w * sX[j * 132 + 64 + p];
        const float* br = &sB[j * 132];
        float bg[16], bh2[16];
#pragma unroll
        for (int q = 0; q < 4; q++) {
            *(float4*)&bg[4 * q]  = *(const float4*)&br[n0 + 4 * q];
            *(float4*)&bh2[4 * q] = *(const float4*)&br[64 + n0 + 4 * q];
        }
#pragma unroll
        for (int jn = 0; jn < 16; jn++)
            st[jn] += bg[jn] * wx0 + bh2[jn] * wx1;
    }
    size_t so = (((size_t)(b * 16 + c) * 32 + h) * 4096);
#pragma unroll
    for (int jn = 0; jn < 16; jn++)
        g_st[so + (size_t)(n0 + jn) * 64 + p] = st[jn];
}

/* ------------------------------------------------------------------ */
/* 7. inter-chunk state scan (16 steps)                                */
/* ------------------------------------------------------------------ */
__global__ __launch_bounds__(256) void scan_chunks_kernel()
{
    int b = blockIdx.x >> 5, h = blockIdx.x & 31;
    int tid = threadIdx.x;
    float S[16];
#pragma unroll
    for (int j = 0; j < 16; j++) S[j] = 0.f;
    for (int c = 0; c < 16; c++) {
        float cdec = expf(g_cum[((size_t)(b * 2048 + c * 128 + 127)) * 32 + h]);
        size_t off0 = (((size_t)(b * 16 + c) * 32 + h) * 4096);
#pragma unroll
        for (int j = 0; j < 16; j++) {
            size_t off = off0 + tid + j * 256;
            g_Sprev[off] = S[j];
            S[j] = cdec * S[j] + g_st[off];
        }
    }
}

/* ------------------------------------------------------------------ */
/* 8. y += SCALE * dec_in * (C @ Sprev)                                */
/* ------------------------------------------------------------------ */
#define SMEM_INTER_FLOATS (64*68 + 128*68 + 128)
__global__ __launch_bounds__(256) void inter_kernel()
{
    extern __shared__ float sm[];
    float* sS = sm;
    float* sC = sm + 64 * 68;
    float* sDec = sC + 128 * 68;
    int h = blockIdx.x, c = blockIdx.y, b = blockIdx.z;
    int tid = threadIdx.x;
    int t0 = c * 128;
    size_t rb = (size_t)b * T_ + t0;
    size_t soff = (((size_t)(b * 16 + c) * 32 + h) * 4096);

    for (int i = tid; i < 4096; i += 256)
        sS[(i >> 6) * 68 + (i & 63)] = g_Sprev[soff + i];
    for (int i = tid; i < 128 * 64; i += 256) {
        int l = i >> 6, n = i & 63;
        sC[l * 68 + n] = g_Cr[(rb + l) * 64 + n];
    }
    if (tid < 128) sDec[tid] = expf(g_cum[(rb + tid) * 32 + h]);
    __syncthreads();

    int pg = tid & 15, p0 = pg << 2, lg = tid >> 4;
#pragma unroll
    for (int jl = 0; jl < 8; jl++) {
        int l = lg + (jl << 4);
        float a0 = 0.f, a1 = 0.f, a2 = 0.f, a3 = 0.f;
#pragma unroll
        for (int n = 0; n < 64; n++) {
            float cv = sC[l * 68 + n];
            const float* sp = &sS[n * 68 + p0];
            a0 += cv * sp[0]; a1 += cv * sp[1];
            a2 += cv * sp[2]; a3 += cv * sp[3];
        }
        float coef = SCALE_F * sDec[l];
        float* yp = &g_y[(rb + l) * (size_t)DI_ + h * 64 + p0];
        yp[0] += coef * a0; yp[1] += coef * a1;
        yp[2] += coef * a2; yp[3] += coef * a3;
    }
}

/* ------------------------------------------------------------------ */
/* 9. y = rms(y * silu(z))                                             */
/* ------------------------------------------------------------------ */
__global__ __launch_bounds__(256) void gate_kernel()
{
    int row = blockIdx.x;
    int tid = threadIdx.x, lane = tid & 31, w = tid >> 5;
    const float* z = g_proj + (size_t)row * DP_;
    float* y = g_y + (size_t)row * DI_;
    float v[8];
    float ss = 0.f;
#pragma unroll
    for (int j = 0; j < 8; j++) {
        int i = tid + j * 256;
        float zv = z[i];
        float sz = zv / (1.f + expf(-zv));
        float vv = y[i] * sz;
        v[j] = vv;
        ss += vv * vv;
    }
#pragma unroll
    for (int o = 16; o > 0; o >>= 1) ss += __shfl_xor_sync(0xffffffffu, ss, o);
    __shared__ float red[8];
    if (lane == 0) red[w] = ss;
    __syncthreads();
    float tot = red[0] + red[1] + red[2] + red[3] + red[4] + red[5] + red[6] + red[7];
    float rinv = rsqrtf(tot * (1.f / 2048.f) + EPS_F);
#pragma unroll
    for (int j = 0; j < 8; j++) y[tid + j * 256] = v[j] * rinv;
}

/* ------------------------------------------------------------------ */
extern "C" void kernel_launch(void* const* d_in, const int* in_sizes, int n_in,
                              void* d_out, int out_size)
{
    const float* x       = (const float*)d_in[0];
    const float* W_in    = (const float*)d_in[1];
    const float* A_log   = (const float*)d_in[2];
    const float* dt_bias = (const float*)d_in[3];
    const float* Bnb     = (const float*)d_in[4];
    const float* Cnb     = (const float*)d_in[5];
    const float* W_out   = (const float*)d_in[6];
    float* out = (float*)d_out;

    void *p_proj = 0, *p_y = 0;
    cudaGetSymbolAddress(&p_proj, g_proj);
    cudaGetSymbolAddress(&p_y, g_y);

    cudaFuncSetAttribute(gemm_bf16x3, cudaFuncAttributeMaxDynamicSharedMemorySize,
                         GEMM_SMEM_BYTES);
    cudaFuncSetAttribute(s_kernel, cudaFuncAttributeMaxDynamicSharedMemorySize,
                         SMEM_S_FLOATS * 4);
    cudaFuncSetAttribute(chunk_kernel, cudaFuncAttributeMaxDynamicSharedMemorySize,
                         SMEM_CHUNK_FLOATS * 4);
    cudaFuncSetAttribute(inter_kernel, cudaFuncAttributeMaxDynamicSharedMemorySize,
                         SMEM_INTER_FLOATS * 4);

    /* 1. in-proj */
    gemm_bf16x3<<<dim3((DP_ + 127) / 128, RB_ / 128), 256, GEMM_SMEM_BYTES>>>(
        x, W_in, (float*)p_proj, RB_, DP_, DM_);
    /* 2. activations */
    act_kernel<<<RB_, 128>>>(A_log, dt_bias, Bnb, Cnb);
    /* 3. angle scan */
    scan_ang_kernel<<<B_ * 32, 256>>>();
    /* 4. rope */
    rope_kernel<<<RB_, 32>>>();
    /* 5. chunk cumsum */
    cum_kernel<<<B_ * NC_, 128>>>();
    /* 5b. shared dot matrix */
    s_kernel<<<dim3(NC_, B_), 256, SMEM_S_FLOATS * 4>>>();
    /* 6. fused chunk */
    chunk_kernel<<<dim3(H_, NC_, B_), 256, SMEM_CHUNK_FLOATS * 4>>>();
    /* 7. state scan */
    scan_chunks_kernel<<<B_ * H_, 256>>>();
    /* 8. inter */
    inter_kernel<<<dim3(H_, NC_, B_), 256, SMEM_INTER_FLOATS * 4>>>();
    /* 9. gate + rms */
    gate_kernel<<<RB_, 256>>>();
    /* 10. out-proj */
    gemm_bf16x3<<<dim3(DM_ / 128, RB_ / 128), 256, GEMM_SMEM_BYTES>>>(
        (const float*)p_y, W_out, out, RB_, DM_, DI_);
}